// round 14
// baseline (speedup 1.0000x reference)
#include <cuda_runtime.h>
#include <math.h>
#include <stdint.h>

#define N0    4096
#define EDGES 65536
#define HID   128

// ---------------- device global scratch ----------------
__device__ int   dA1cols[(size_t)2048 * 2048];
__device__ float dA1vals[(size_t)2048 * 2048];
__device__ int   dA1cnt[2048];
__device__ float dA2[(size_t)1024 * 1024];
__device__ float dA3[(size_t)512 * 512];
__device__ float dA4[(size_t)256 * 256];
__device__ float dSplit[1 << 20];              // split-K partials (4 MB)
__device__ float dQbuf[(size_t)1024 * 512];
__device__ float dX0[N0 * HID];
__device__ float dX1[2048 * HID];
__device__ float dX2[1024 * HID];
__device__ float dX3[512 * HID];
__device__ float dHa[N0 * HID];
__device__ float dHb[N0 * HID];
__device__ float dT1[N0 * HID];
__device__ float dT2[N0 * HID];
__device__ float dScore[N0];
__device__ float dValsArr[N0];
__device__ float dHWo[N0];
__device__ float dGv[N0];
__device__ float dPn[4];
__device__ int   dPerm0[2048];
__device__ int   dPerm1[1024];
__device__ int   dPerm2[512];
__device__ int   dPerm3[256];
__device__ int   dInv0[4096];
__device__ int   dInv1[2048];
__device__ int   dInv2[1024];
__device__ int   dInv3[512];
__device__ float dDis0[4096];
__device__ float dDis1[2048];
__device__ float dDis2[1024];
__device__ float dDis3[512];
__device__ float dDis4[256];
__device__ int   dRp[N0 + 1];
__device__ int   dColA[EDGES];
__device__ int   dCnt[N0];
__device__ int   dCur[N0];

// ---------------- packed f32x2 FMA ----------------
__device__ __forceinline__ void ffma2(unsigned long long& d, unsigned long long a,
                                      unsigned long long b) {
    asm("fma.rn.f32x2 %0, %1, %2, %0;" : "+l"(d) : "l"(a), "l"(b));
}

// ---------------- setup kernels ----------------

__global__ void k_zero2(int* a, int* b, int n) {
    int i = blockIdx.x * blockDim.x + threadIdx.x;
    if (i < n) { a[i] = 0; b[i] = 0; }
}

__global__ void k_count(const int* __restrict__ ei, int* __restrict__ cnt) {
    int e = blockIdx.x * blockDim.x + threadIdx.x;
    if (e < EDGES) atomicAdd(&cnt[ei[EDGES + e]], 1);
}

// warp-based exclusive scan of 4096 counts + fused dis0 + fused p-norms
__global__ void k_scan_dis(const int* __restrict__ cnt, int* __restrict__ rp,
                           float* __restrict__ dis,
                           const float* __restrict__ p_pool, float* __restrict__ pn) {
    __shared__ int wsum[32];
    int tid = threadIdx.x;           // 1024 threads
    int base = tid * 4;
    int4 c = *(const int4*)(cnt + base);
    int s1 = c.x, s2 = s1 + c.y, s3 = s2 + c.z, s4 = s3 + c.w;
    int lane = tid & 31, w = tid >> 5;
    int v = s4;
#pragma unroll
    for (int o = 1; o < 32; o <<= 1) {
        int nv = __shfl_up_sync(~0u, v, o);
        if (lane >= o) v += nv;
    }
    if (lane == 31) wsum[w] = v;
    __syncthreads();
    if (w == 0) {
        int x = wsum[lane];
#pragma unroll
        for (int o = 1; o < 32; o <<= 1) {
            int nv = __shfl_up_sync(~0u, x, o);
            if (lane >= o) x += nv;
        }
        wsum[lane] = x;
    }
    __syncthreads();
    int warpBase = (w > 0) ? wsum[w - 1] : 0;
    int tbase = warpBase + v - s4;
    rp[base + 1] = tbase + s1;
    rp[base + 2] = tbase + s2;
    rp[base + 3] = tbase + s3;
    rp[base + 4] = tbase + s4;
    if (tid == 0) rp[0] = 0;
    dis[base]     = rsqrtf((float)c.x + 2.0f);
    dis[base + 1] = rsqrtf((float)c.y + 2.0f);
    dis[base + 2] = rsqrtf((float)c.z + 2.0f);
    dis[base + 3] = rsqrtf((float)c.w + 2.0f);
    if (w < 4) {
        float s = 0.0f;
        for (int cc = lane; cc < HID; cc += 32) {
            float pv = p_pool[w * HID + cc];
            s += pv * pv;
        }
#pragma unroll
        for (int o = 16; o; o >>= 1) s += __shfl_down_sync(0xffffffffu, s, o);
        if (lane == 0) pn[w] = sqrtf(s);
    }
}

__global__ void k_fill(const int* __restrict__ ei, const int* __restrict__ rp,
                       int* __restrict__ cur, int* __restrict__ colA) {
    int e = blockIdx.x * blockDim.x + threadIdx.x;
    if (e < EDGES) {
        int s = ei[e], d = ei[EDGES + e];
        int pos = rp[d] + atomicAdd(&cur[d], 1);
        colA[pos] = s;
    }
}

// ---------------- sparse augment ----------------

// Level-1: A1 = offdiag((B@B)[perm,perm]) sparse; also writes dis1.
// Compaction via 2-level warp scan (order identical to Hillis-Steele version).
__global__ void k_spgemm1(const int* __restrict__ rp, const int* __restrict__ colA,
                          const int* __restrict__ perm, const int* __restrict__ inv,
                          int* __restrict__ oCols, float* __restrict__ oVals,
                          int* __restrict__ oCnt, float* __restrict__ dis1) {
    __shared__ float accs[2048];
    __shared__ int   wtot[8];
    __shared__ float wft[8];
    int r = blockIdx.x;
    int pr = perm[r];
    int tid = threadIdx.x;
    int lane = tid & 31, w = tid >> 5;
    for (int i = tid; i < 2048; i += blockDim.x) accs[i] = 0.0f;
    __syncthreads();
    int s = rp[pr], e = rp[pr + 1];
    int outerCnt = (e - s) + 1;
    for (int oi = tid; oi < outerCnt; oi += blockDim.x) {
        int m = (oi < e - s) ? colA[s + oi] : pr;
        if (oi < e - s && m == pr) continue;
        int s2 = rp[m], e2 = rp[m + 1];
        for (int t = s2; t < e2; t++) {
            int j = colA[t];
            if (j == m) continue;
            int c = inv[j];
            if (c >= 0) atomicAdd(&accs[c], 1.0f);
        }
        int cm = inv[m];
        if (cm >= 0) atomicAdd(&accs[cm], 1.0f);
    }
    __syncthreads();
    int base = tid * 8;
    int lc = 0;
    float ls = 0.0f;
#pragma unroll
    for (int j = 0; j < 8; j++) {
        int c = base + j;
        float v = accs[c];
        if (c != r && v != 0.0f) { lc++; ls += v; }
    }
    int li = lc;
    float lf = ls;
#pragma unroll
    for (int o = 1; o < 32; o <<= 1) {
        int nv = __shfl_up_sync(~0u, li, o);
        if (lane >= o) li += nv;
        lf += __shfl_xor_sync(~0u, lf, o);
    }
    if (lane == 31) { wtot[w] = li; wft[w] = lf; }
    __syncthreads();
    int basei = 0;
    for (int ww = 0; ww < w; ww++) basei += wtot[ww];
    int pos = basei + li - lc;
#pragma unroll
    for (int j = 0; j < 8; j++) {
        int c = base + j;
        float v = accs[c];
        if (c != r && v != 0.0f) {
            oCols[(size_t)r * 2048 + pos] = c;
            oVals[(size_t)r * 2048 + pos] = v;
            pos++;
        }
    }
    if (tid == 0) {
        int tot = 0;
        float ftot = 0.0f;
#pragma unroll
        for (int ww = 0; ww < 8; ww++) { tot += wtot[ww]; ftot += wft[ww]; }
        oCnt[r] = tot;
        dis1[r] = rsqrtf(ftot + 2.0f);
    }
}

// Level-2: A2 dense = offdiag((B1@B1)[perm,perm]); fused dis2.
__global__ void k_spgemm2(const int* __restrict__ oCols, const float* __restrict__ oVals,
                          const int* __restrict__ oCnt,
                          const int* __restrict__ perm, const int* __restrict__ invg,
                          float* __restrict__ A2, float* __restrict__ dis2, int kOut) {
    __shared__ float accs[1024];
    __shared__ int   sinv[2048];
    __shared__ float red[8];
    int r = blockIdx.x;
    int pr = perm[r];
    int tid = threadIdx.x;
    for (int i = tid; i < kOut; i += 256) accs[i] = 0.0f;
    for (int i = tid; i < 2048; i += 256) sinv[i] = invg[i];
    __syncthreads();
    int cnt = oCnt[pr];
    const int*   cols = oCols + (size_t)pr * 2048;
    const float* vals = oVals + (size_t)pr * 2048;
    int lane = tid & 31, w = tid >> 5;
    for (int oi = w; oi <= cnt; oi += 8) {
        int m; float vOut;
        if (oi < cnt) { m = cols[oi]; vOut = vals[oi]; }
        else          { m = pr;       vOut = 1.0f; }
        int cnt2 = oCnt[m];
        const int*   cols2 = oCols + (size_t)m * 2048;
        const float* vals2 = oVals + (size_t)m * 2048;
        for (int t2 = lane; t2 < cnt2; t2 += 32) {
            int c = sinv[cols2[t2]];
            if (c >= 0) atomicAdd(&accs[c], vOut * vals2[t2]);
        }
        if (lane == 0) {
            int cm = sinv[m];
            if (cm >= 0) atomicAdd(&accs[cm], vOut);
        }
    }
    __syncthreads();
    float s = 0.0f;
    for (int c = tid; c < kOut; c += 256) {
        float v = (c == r) ? 0.0f : accs[c];
        s += v;
        A2[(size_t)r * kOut + c] = v;
    }
#pragma unroll
    for (int off = 16; off; off >>= 1) s += __shfl_down_sync(0xffffffffu, s, off);
    if (lane == 0) red[w] = s;
    __syncthreads();
    if (tid == 0) {
        float tot = 0.0f;
#pragma unroll
        for (int i = 0; i < 8; i++) tot += red[i];
        dis2[r] = rsqrtf(tot + 2.0f);
    }
}

// ---------------- sparse GCN propagation (warp-per-row, float4, fused score) ----------------

__global__ void k_spmm0_ep(const int* __restrict__ rp, const int* __restrict__ colA,
                           const float* __restrict__ T2, const float* __restrict__ T1,
                           const float* __restrict__ dis, const float* __restrict__ b,
                           float* __restrict__ out, int relu,
                           const float* __restrict__ p, const float* __restrict__ pnP,
                           float* __restrict__ score) {
    int w = threadIdx.x >> 5, lane = threadIdx.x & 31;
    int i = blockIdx.x * 8 + w;
    int s = rp[i], e = rp[i + 1];
    float4 acc = make_float4(0.f, 0.f, 0.f, 0.f);
#pragma unroll 4
    for (int t = s; t < e; t++) {
        int c = colA[t];
        float4 tv = *(const float4*)(T2 + (size_t)c * HID + lane * 4);
        acc.x += tv.x; acc.y += tv.y; acc.z += tv.z; acc.w += tv.w;
    }
    float di = dis[i];
    float4 t1 = *(const float4*)(T1 + (size_t)i * HID + lane * 4);
    float4 bv = *(const float4*)(b + lane * 4);
    float4 o;
    o.x = di * (acc.x + 2.0f * di * t1.x) + bv.x;
    o.y = di * (acc.y + 2.0f * di * t1.y) + bv.y;
    o.z = di * (acc.z + 2.0f * di * t1.z) + bv.z;
    o.w = di * (acc.w + 2.0f * di * t1.w) + bv.w;
    if (relu) {
        o.x = fmaxf(o.x, 0.f); o.y = fmaxf(o.y, 0.f);
        o.z = fmaxf(o.z, 0.f); o.w = fmaxf(o.w, 0.f);
    }
    *(float4*)(out + (size_t)i * HID + lane * 4) = o;
    if (p) {
        float4 pv = *(const float4*)(p + lane * 4);
        float d = o.x * pv.x + o.y * pv.y + o.z * pv.z + o.w * pv.w;
#pragma unroll
        for (int off = 16; off; off >>= 1) d += __shfl_down_sync(0xffffffffu, d, off);
        if (lane == 0) score[i] = d / pnP[0];
    }
}

__global__ void k_spmm1_ep(const int* __restrict__ oCols, const float* __restrict__ oVals,
                           const int* __restrict__ oCnt,
                           const float* __restrict__ T2, const float* __restrict__ T1,
                           const float* __restrict__ dis, const float* __restrict__ b,
                           float* __restrict__ out, int relu,
                           const float* __restrict__ p, const float* __restrict__ pnP,
                           float* __restrict__ score) {
    int w = threadIdx.x >> 5, lane = threadIdx.x & 31;
    int i = blockIdx.x * 8 + w;
    int cnt = oCnt[i];
    const int*   cols = oCols + (size_t)i * 2048;
    const float* vals = oVals + (size_t)i * 2048;
    float4 acc = make_float4(0.f, 0.f, 0.f, 0.f);
    int t = 0;
    for (; t + 4 <= cnt; t += 4) {
        int4   c4 = *(const int4*)(cols + t);
        float4 v4 = *(const float4*)(vals + t);
        float4 a0 = *(const float4*)(T2 + (size_t)c4.x * HID + lane * 4);
        float4 a1 = *(const float4*)(T2 + (size_t)c4.y * HID + lane * 4);
        float4 a2 = *(const float4*)(T2 + (size_t)c4.z * HID + lane * 4);
        float4 a3 = *(const float4*)(T2 + (size_t)c4.w * HID + lane * 4);
        acc.x += v4.x * a0.x; acc.y += v4.x * a0.y; acc.z += v4.x * a0.z; acc.w += v4.x * a0.w;
        acc.x += v4.y * a1.x; acc.y += v4.y * a1.y; acc.z += v4.y * a1.z; acc.w += v4.y * a1.w;
        acc.x += v4.z * a2.x; acc.y += v4.z * a2.y; acc.z += v4.z * a2.z; acc.w += v4.z * a2.w;
        acc.x += v4.w * a3.x; acc.y += v4.w * a3.y; acc.z += v4.w * a3.z; acc.w += v4.w * a3.w;
    }
    for (; t < cnt; t++) {
        int c = cols[t];
        float v = vals[t];
        float4 tv = *(const float4*)(T2 + (size_t)c * HID + lane * 4);
        acc.x += v * tv.x; acc.y += v * tv.y; acc.z += v * tv.z; acc.w += v * tv.w;
    }
    float di = dis[i];
    float4 t1 = *(const float4*)(T1 + (size_t)i * HID + lane * 4);
    float4 bv = *(const float4*)(b + lane * 4);
    float4 o;
    o.x = di * (acc.x + 2.0f * di * t1.x) + bv.x;
    o.y = di * (acc.y + 2.0f * di * t1.y) + bv.y;
    o.z = di * (acc.z + 2.0f * di * t1.z) + bv.z;
    o.w = di * (acc.w + 2.0f * di * t1.w) + bv.w;
    if (relu) {
        o.x = fmaxf(o.x, 0.f); o.y = fmaxf(o.y, 0.f);
        o.z = fmaxf(o.z, 0.f); o.w = fmaxf(o.w, 0.f);
    }
    *(float4*)(out + (size_t)i * HID + lane * 4) = o;
    if (p) {
        float4 pv = *(const float4*)(p + lane * 4);
        float d = o.x * pv.x + o.y * pv.y + o.z * pv.z + o.w * pv.w;
#pragma unroll
        for (int off = 16; off; off >>= 1) d += __shfl_down_sync(0xffffffffu, d, off);
        if (lane == 0) score[i] = d / pnP[0];
    }
}

// ---------------- dense kernels ----------------

__global__ void k_encoder(const float* __restrict__ x, const float* __restrict__ W,
                          const float* __restrict__ b, float* __restrict__ h) {
    int i = blockIdx.x;
    int c = threadIdx.x;
    float acc = b[c];
#pragma unroll
    for (int k = 0; k < 16; k++) acc += x[i * 16 + k] * W[k * HID + c];
    h[i * HID + c] = acc;
}

// Split-K SGEMM (packed f32x2) with A-row virtualization (pool/unpool fused).
// If T1o != null (requires gridDim.z == 1): direct epilogue T1o=acc, T2o=dis*acc.
__global__ void k_gemm_sk(const float* __restrict__ A, const float* __restrict__ B,
                          float* __restrict__ P, int M, int N, int K, int Kc,
                          const int* __restrict__ perm, const float* __restrict__ vals,
                          const float* __restrict__ Xs, const int* __restrict__ inv,
                          float* __restrict__ T1o, float* __restrict__ T2o,
                          const float* __restrict__ disEp) {
    __shared__ float Asd[16][132];
    __shared__ float Bs[16][64];
    int t = threadIdx.x;
    int m0 = blockIdx.y * 64, n0 = blockIdx.x * 64;
    int kBeg = blockIdx.z * Kc;
    int ar = t >> 2, ac = (t & 3) << 2;
    int bk = t >> 4, bn = (t & 15) << 2;
    int tm = (t >> 4) << 2, tn = (t & 15) << 2;
    int row = m0 + ar;

    const float* Aptr;
    const float* Xptr = nullptr;
    float gate = 1.0f;
    bool haveA = true;
    if (perm) {
        Aptr = A + (size_t)perm[row] * K + kBeg + ac;
        gate = tanhf(vals[row]);
    } else if (Xs) {
        int iv = inv[row];
        Xptr = Xs + (size_t)row * K + kBeg + ac;
        haveA = (iv >= 0);
        Aptr = haveA ? A + (size_t)iv * K + kBeg + ac : Xptr;
    } else {
        Aptr = A + (size_t)row * K + kBeg + ac;
    }

    unsigned long long acc[4][2];
#pragma unroll
    for (int a = 0; a < 4; a++) { acc[a][0] = 0ull; acc[a][1] = 0ull; }

    const float* Bptr = B + (size_t)(kBeg + bk) * N + n0 + bn;

    auto loadA = [&](int k0) -> float4 {
        float4 v = *(const float4*)(Aptr + k0);
        if (Xs) {
            if (haveA) {
                float4 xv = *(const float4*)(Xptr + k0);
                v.x += xv.x; v.y += xv.y; v.z += xv.z; v.w += xv.w;
            }
        } else if (perm) {
            v.x *= gate; v.y *= gate; v.z *= gate; v.w *= gate;
        }
        return v;
    };

    float4 av = loadA(0);
    float4 bv = *(const float4*)Bptr;
    for (int k0 = 0; k0 < Kc; k0 += 16) {
        *(float2*)&Asd[ac + 0][2 * ar] = make_float2(av.x, av.x);
        *(float2*)&Asd[ac + 1][2 * ar] = make_float2(av.y, av.y);
        *(float2*)&Asd[ac + 2][2 * ar] = make_float2(av.z, av.z);
        *(float2*)&Asd[ac + 3][2 * ar] = make_float2(av.w, av.w);
        *(float4*)&Bs[bk][bn] = bv;
        __syncthreads();
        if (k0 + 16 < Kc) {
            av = loadA(k0 + 16);
            bv = *(const float4*)(Bptr + (size_t)(k0 + 16) * N);
        }
#pragma unroll
        for (int kk = 0; kk < 16; kk++) {
            ulonglong2 a01 = *(const ulonglong2*)&Asd[kk][2 * tm];
            ulonglong2 a23 = *(const ulonglong2*)&Asd[kk][2 * tm + 4];
            ulonglong2 b01 = *(const ulonglong2*)&Bs[kk][tn];
            ffma2(acc[0][0], a01.x, b01.x); ffma2(acc[0][1], a01.x, b01.y);
            ffma2(acc[1][0], a01.y, b01.x); ffma2(acc[1][1], a01.y, b01.y);
            ffma2(acc[2][0], a23.x, b01.x); ffma2(acc[2][1], a23.x, b01.y);
            ffma2(acc[3][0], a23.y, b01.x); ffma2(acc[3][1], a23.y, b01.y);
        }
        __syncthreads();
    }
    if (T1o) {
#pragma unroll
        for (int a = 0; a < 4; a++) {
            int gm = m0 + tm + a;
            float di = disEp[gm];
            float4 o;
            o.x = __uint_as_float((unsigned)acc[a][0]);
            o.y = __uint_as_float((unsigned)(acc[a][0] >> 32));
            o.z = __uint_as_float((unsigned)acc[a][1]);
            o.w = __uint_as_float((unsigned)(acc[a][1] >> 32));
            *(float4*)&T1o[(size_t)gm * N + n0 + tn] = o;
            float4 o2 = make_float4(di * o.x, di * o.y, di * o.z, di * o.w);
            *(float4*)&T2o[(size_t)gm * N + n0 + tn] = o2;
        }
        return;
    }
    float* Pp = P + (size_t)blockIdx.z * M * N;
#pragma unroll
    for (int a = 0; a < 4; a++) {
        int gm = m0 + tm + a;
        float4 o;
        o.x = __uint_as_float((unsigned)acc[a][0]);
        o.y = __uint_as_float((unsigned)(acc[a][0] >> 32));
        o.z = __uint_as_float((unsigned)acc[a][1]);
        o.w = __uint_as_float((unsigned)(acc[a][1] >> 32));
        *(float4*)&Pp[(size_t)gm * N + n0 + tn] = o;
    }
}

// Augment GEMM: A row-gathered: A[r,c] = B1[perm[r], c]
__global__ void k_gemm_aug(const float* __restrict__ Aprev, const int* __restrict__ perm,
                           const float* __restrict__ B, float* __restrict__ P,
                           int Mk, int K, int Kc) {
    __shared__ float Asd[16][132];
    __shared__ float Bs[16][64];
    int t = threadIdx.x;
    int m0 = blockIdx.y * 64, n0 = blockIdx.x * 64;
    int kBeg = blockIdx.z * Kc;
    int ar = t >> 2, ac = (t & 3) << 2;
    int bk = t >> 4, bn = (t & 15) << 2;
    int tm = (t >> 4) << 2, tn = (t & 15) << 2;
    int pr = perm[m0 + ar];

    unsigned long long acc[4][2];
#pragma unroll
    for (int a = 0; a < 4; a++) { acc[a][0] = 0ull; acc[a][1] = 0ull; }

    const float* Aptr = Aprev + (size_t)pr * K + kBeg + ac;
    const float* Bptr = B + (size_t)(kBeg + bk) * Mk + n0 + bn;

    auto loadA = [&](int k0) -> float4 {
        float4 v = *(const float4*)(Aptr + k0);
        int cbase = kBeg + k0 + ac;
        if (pr >= cbase && pr < cbase + 4) ((float*)&v)[pr - cbase] = 1.0f;
        return v;
    };

    float4 av = loadA(0);
    float4 bv = *(const float4*)Bptr;
    for (int k0 = 0; k0 < Kc; k0 += 16) {
        *(float2*)&Asd[ac + 0][2 * ar] = make_float2(av.x, av.x);
        *(float2*)&Asd[ac + 1][2 * ar] = make_float2(av.y, av.y);
        *(float2*)&Asd[ac + 2][2 * ar] = make_float2(av.z, av.z);
        *(float2*)&Asd[ac + 3][2 * ar] = make_float2(av.w, av.w);
        *(float4*)&Bs[bk][bn] = bv;
        __syncthreads();
        if (k0 + 16 < Kc) {
            av = loadA(k0 + 16);
            bv = *(const float4*)(Bptr + (size_t)(k0 + 16) * Mk);
        }
#pragma unroll
        for (int kk = 0; kk < 16; kk++) {
            ulonglong2 a01 = *(const ulonglong2*)&Asd[kk][2 * tm];
            ulonglong2 a23 = *(const ulonglong2*)&Asd[kk][2 * tm + 4];
            ulonglong2 b01 = *(const ulonglong2*)&Bs[kk][tn];
            ffma2(acc[0][0], a01.x, b01.x); ffma2(acc[0][1], a01.x, b01.y);
            ffma2(acc[1][0], a01.y, b01.x); ffma2(acc[1][1], a01.y, b01.y);
            ffma2(acc[2][0], a23.x, b01.x); ffma2(acc[2][1], a23.x, b01.y);
            ffma2(acc[3][0], a23.y, b01.x); ffma2(acc[3][1], a23.y, b01.y);
        }
        __syncthreads();
    }
    float* Pp = P + (size_t)blockIdx.z * Mk * Mk;
#pragma unroll
    for (int a = 0; a < 4; a++) {
        int gm = m0 + tm + a;
        float4 o;
        o.x = __uint_as_float((unsigned)acc[a][0]);
        o.y = __uint_as_float((unsigned)(acc[a][0] >> 32));
        o.z = __uint_as_float((unsigned)acc[a][1]);
        o.w = __uint_as_float((unsigned)(acc[a][1] >> 32));
        *(float4*)&Pp[(size_t)gm * Mk + n0 + tn] = o;
    }
}

// Reduce split-K partials + fused epilogue.
// mode 0: C = sum (T1); C2 = dis[row]*sum (T2)
// mode 2: C = [relu]( dis*(sum + 2*dis*C2in) + bias ); optional fused score.
__global__ void k_reduce(const float* __restrict__ P, int S, int M, int N, int mode,
                         const float* __restrict__ dis, const float* __restrict__ bias,
                         float* __restrict__ C, float* __restrict__ C2, int relu,
                         const float* __restrict__ p, const float* __restrict__ pnP,
                         float* __restrict__ scoreP) {
    int tid = threadIdx.x;
    int idx = blockIdx.x * blockDim.x + tid;
    int total = M * N;
    if (idx >= total) return;
    float s = 0.0f;
    for (int z = 0; z < S; z++) s += P[(size_t)z * total + idx];
    int gm = idx / N;
    int gn = idx - gm * N;
    if (mode == 0) {
        C[idx] = s;
        C2[idx] = dis[gm] * s;
    } else {
        float di = dis[gm];
        float v = di * (s + 2.0f * di * C2[idx]) + bias[gn];
        if (relu) v = fmaxf(v, 0.0f);
        C[idx] = v;
        if (scoreP) {
            __shared__ float sm[256];
            sm[tid] = v * p[gn];
            __syncthreads();
            for (int o = 64; o > 0; o >>= 1) {
                if ((tid & 127) < o) sm[tid] += sm[tid + o];
                __syncthreads();
            }
            if ((tid & 127) == 0) scoreP[gm] = sm[tid] / pnP[0];
        }
    }
}

// Per-row reduce of augment partials: zero diag, write A, rowsum -> dis.
__global__ void k_reduce_dis(const float* __restrict__ P, int S, int k,
                             float* __restrict__ A, float* __restrict__ dis) {
    __shared__ float red[8];
    int r = blockIdx.x;
    int tid = threadIdx.x;
    float s = 0.0f;
    for (int c = tid; c < k; c += 256) {
        float v = 0.0f;
        for (int z = 0; z < S; z++) v += P[(size_t)z * k * k + (size_t)r * k + c];
        if (c == r) v = 0.0f;
        s += v;
        A[(size_t)r * k + c] = v;
    }
    int lane = tid & 31, w = tid >> 5;
#pragma unroll
    for (int off = 16; off; off >>= 1) s += __shfl_down_sync(0xffffffffu, s, off);
    if (lane == 0) red[w] = s;
    __syncthreads();
    if (tid == 0) {
        float tot = 0.0f;
#pragma unroll
        for (int i = 0; i < 8; i++) tot += red[i];
        dis[r] = rsqrtf(tot + 2.0f);
    }
}

// Q[m, c] = B1[m, perm[c]]  (column gather with diag patch)
__global__ void k_gather_cols(const float* __restrict__ A, const int* __restrict__ perm,
                              float* __restrict__ Q, int k, int n) {
    size_t idx = (size_t)blockIdx.x * blockDim.x + threadIdx.x;
    if (idx < (size_t)n * k) {
        int m = (int)(idx / k), c = (int)(idx % k);
        int pc = perm[c];
        float v = A[(size_t)m * n + pc];
        Q[idx] = (m == pc) ? 1.0f : v;
    }
}

// ---------------- pooling ----------------

// Packed-key bitonic sort with warp-fused tail (j<=16 via shfl_xor).
__global__ void k_topk_sort(const float* __restrict__ score, int n, int k,
                            int* __restrict__ perm, float* __restrict__ vals,
                            int* __restrict__ inv) {
    __shared__ unsigned long long key[4096];
    int tid = threadIdx.x;
    int lane = tid & 31, w = tid >> 5;
    int numWarps = blockDim.x >> 5;
    for (int i = tid; i < n; i += blockDim.x) {
        unsigned u = __float_as_uint(score[i]);
        u = (u & 0x80000000u) ? ~u : (u | 0x80000000u);
        key[i] = ((unsigned long long)u << 32) | (unsigned)(~i);
        inv[i] = -1;
    }
    __syncthreads();
    int half = n >> 1;
    for (int ksz = 2; ksz <= n; ksz <<= 1) {
        for (int j = ksz >> 1; j >= 32; j >>= 1) {
            for (int p = tid; p < half; p += blockDim.x) {
                int idx = ((p & ~(j - 1)) << 1) | (p & (j - 1));
                int ixj = idx | j;
                unsigned long long a = key[idx], b = key[ixj];
                bool dir = (idx & ksz) == 0;
                if (dir ? (b > a) : (a > b)) { key[idx] = b; key[ixj] = a; }
            }
            __syncthreads();
        }
        int jstart = (ksz >> 1 < 16) ? (ksz >> 1) : 16;
        for (int seg = w; seg < (n >> 5); seg += numWarps) {
            int idx = (seg << 5) | lane;
            unsigned long long v = key[idx];
            bool dir = (idx & ksz) == 0;
            for (int j = jstart; j >= 1; j >>= 1) {
                unsigned long long o = __shfl_xor_sync(0xffffffffu, v, j);
                bool lower = (lane & j) == 0;
                bool takeMax = (dir == lower);
                bool gt = (v > o);
                v = (takeMax == gt) ? v : o;
            }
            key[idx] = v;
        }
        __syncthreads();
    }
    for (int r = tid; r < k; r += blockDim.x) {
        int idx = (int)(~(unsigned)key[r]);
        perm[r] = idx;
        vals[r] = score[idx];
        inv[idx] = r;
    }
}

// ---------------- final conv (unpool fused) ----------------

__global__ void k_hw_out_uf(const float* __restrict__ X0, const float* __restrict__ h,
                            const int* __restrict__ inv, const float* __restrict__ Wout,
                            const float* __restrict__ dis, float* __restrict__ hw,
                            float* __restrict__ g) {
    int i = blockIdx.x;
    int c = threadIdx.x;
    float v = X0[i * HID + c];
    int r = inv[i];
    if (r >= 0) v += h[r * HID + c];
    __shared__ float sm[HID];
    sm[c] = v * Wout[c];
    __syncthreads();
    for (int o = 64; o > 0; o >>= 1) {
        if (c < o) sm[c] += sm[c + o];
        __syncthreads();
    }
    if (c == 0) { hw[i] = sm[0]; g[i] = dis[i] * sm[0]; }
}

__global__ void k_final_sp(const int* __restrict__ rp, const int* __restrict__ colA,
                           const float* __restrict__ g, const float* __restrict__ hw,
                           const float* __restrict__ dis, const float* __restrict__ b,
                           float* __restrict__ out) {
    int i = blockIdx.x * blockDim.x + threadIdx.x;
    if (i < N0) {
        float s = 0.0f;
        int a = rp[i], e = rp[i + 1];
        for (int t = a; t < e; t++) s += g[colA[t]];
        float di = dis[i];
        out[i] = di * (s + 2.0f * di * hw[i]) + b[0];
    }
}

// ---------------- host orchestration ----------------

static float* g_split = nullptr;

// h@W: direct S=1 epilogue when grid large (n>=2048); split-K otherwise.
static void hW(const float* Hin, const float* W, int n, int S, const float* dis,
               const int* perm, const float* vals, const float* Xs, const int* inv,
               float* T1, float* T2) {
    if (n >= 2048) {
        dim3 g(2, n / 64, 1);
        k_gemm_sk<<<g, 256>>>(Hin, W, nullptr, n, HID, HID, HID, perm, vals, Xs, inv,
                              T1, T2, dis);
    } else {
        dim3 g(2, n / 64, S);
        k_gemm_sk<<<g, 256>>>(Hin, W, g_split, n, HID, HID, HID / S, perm, vals, Xs, inv,
                              nullptr, nullptr, nullptr);
        int total = n * HID;
        k_reduce<<<total / 256, 256>>>(g_split, S, n, HID, 0, dis, nullptr,
                                       T1, T2, 0, nullptr, nullptr, nullptr);
    }
}

static void at2(const float* A, const float* T2, const float* T1, int n, int S,
                const float* dis, const float* bias, float* C, int relu,
                const float* p, const float* pnP, float* score) {
    dim3 g(2, n / 64, S);
    k_gemm_sk<<<g, 256>>>(A, T2, g_split, n, HID, n, n / S,
                          nullptr, nullptr, nullptr, nullptr,
                          nullptr, nullptr, nullptr);
    int total = n * HID;
    k_reduce<<<total / 256, 256>>>(g_split, S, n, HID, 2, dis, bias,
                                   C, (float*)T1, relu, p, pnP, score);
}

extern "C" void kernel_launch(void* const* d_in, const int* in_sizes, int n_in,
                              void* d_out, int out_size) {
    const float* x      = (const float*)d_in[0];
    const int*   ei     = (const int*)d_in[1];
    const float* W_enc  = (const float*)d_in[3];
    const float* b_enc  = (const float*)d_in[4];
    const float* W_down = (const float*)d_in[5];
    const float* b_down = (const float*)d_in[6];
    const float* W_up   = (const float*)d_in[7];
    const float* b_up   = (const float*)d_in[8];
    const float* W_out  = (const float*)d_in[9];
    const float* b_out  = (const float*)d_in[10];
    const float* p_pool = (const float*)d_in[11];
    float* out = (float*)d_out;

    float *A2, *A3, *A4, *Qb;
    float *X0, *X1, *X2, *X3, *Ha, *Hb, *T1, *T2;
    float *Score, *Vals, *HWo, *Gv, *Pn;
    float *A1vals;
    int *A1cols, *A1cnt;
    int *P0, *P1, *P2, *P3, *Rp, *ColA, *Cnt, *Cur;
    int *I0, *I1, *I2, *I3;
    float *D0, *D1, *D2, *D3, *D4;
    cudaGetSymbolAddress((void**)&A1cols, dA1cols);
    cudaGetSymbolAddress((void**)&A1vals, dA1vals);
    cudaGetSymbolAddress((void**)&A1cnt, dA1cnt);
    cudaGetSymbolAddress((void**)&A2, dA2);
    cudaGetSymbolAddress((void**)&A3, dA3);
    cudaGetSymbolAddress((void**)&A4, dA4);
    cudaGetSymbolAddress((void**)&g_split, dSplit);
    cudaGetSymbolAddress((void**)&Qb, dQbuf);
    cudaGetSymbolAddress((void**)&X0, dX0);
    cudaGetSymbolAddress((void**)&X1, dX1);
    cudaGetSymbolAddress((void**)&X2, dX2);
    cudaGetSymbolAddress((void**)&X3, dX3);
    cudaGetSymbolAddress((void**)&Ha, dHa);
    cudaGetSymbolAddress((void**)&Hb, dHb);
    cudaGetSymbolAddress((void**)&T1, dT1);
    cudaGetSymbolAddress((void**)&T2, dT2);
    cudaGetSymbolAddress((void**)&Score, dScore);
    cudaGetSymbolAddress((void**)&Vals, dValsArr);
    cudaGetSymbolAddress((void**)&HWo, dHWo);
    cudaGetSymbolAddress((void**)&Gv, dGv);
    cudaGetSymbolAddress((void**)&Pn, dPn);
    cudaGetSymbolAddress((void**)&P0, dPerm0);
    cudaGetSymbolAddress((void**)&P1, dPerm1);
    cudaGetSymbolAddress((void**)&P2, dPerm2);
    cudaGetSymbolAddress((void**)&P3, dPerm3);
    cudaGetSymbolAddress((void**)&I0, dInv0);
    cudaGetSymbolAddress((void**)&I1, dInv1);
    cudaGetSymbolAddress((void**)&I2, dInv2);
    cudaGetSymbolAddress((void**)&I3, dInv3);
    cudaGetSymbolAddress((void**)&D0, dDis0);
    cudaGetSymbolAddress((void**)&D1, dDis1);
    cudaGetSymbolAddress((void**)&D2, dDis2);
    cudaGetSymbolAddress((void**)&D3, dDis3);
    cudaGetSymbolAddress((void**)&D4, dDis4);
    cudaGetSymbolAddress((void**)&Rp, dRp);
    cudaGetSymbolAddress((void**)&ColA, dColA);
    cudaGetSymbolAddress((void**)&Cnt, dCnt);
    cudaGetSymbolAddress((void**)&Cur, dCur);

    // 1) node encoder + CSR of A0 (dis0 + p-norms fused into scan)
    k_encoder<<<N0, HID>>>(x, W_enc, b_enc, Ha);
    k_zero2<<<N0 / 256, 256>>>(Cnt, Cur, N0);
    k_count<<<EDGES / 256, 256>>>(ei, Cnt);
    k_scan_dis<<<1, 1024>>>(Cnt, Rp, D0, p_pool, Pn);
    k_fill<<<EDGES / 256, 256>>>(ei, Rp, Cur, ColA);

    // 2) down conv 0 (sparse, direct-epilogue GEMM, score fused) -> X0, Score
    hW(Ha, W_down, N0, 1, D0, nullptr, nullptr, nullptr, nullptr, T1, T2);
    k_spmm0_ep<<<N0 / 8, 256>>>(Rp, ColA, T2, T1, D0, b_down, X0, 1,
                                p_pool, Pn, Score);

    // 3) down level 1 (sparse A1); pool fused into hW; score fused into spmm
    k_topk_sort<<<1, 1024>>>(Score, 4096, 2048, P0, Vals, I0);
    k_spgemm1<<<2048, 256>>>(Rp, ColA, P0, I0, A1cols, A1vals, A1cnt, D1);
    hW(X0, W_down + 1 * HID * HID, 2048, 1, D1, P0, Vals, nullptr, nullptr, T1, T2);
    k_spmm1_ep<<<2048 / 8, 256>>>(A1cols, A1vals, A1cnt, T2, T1, D1,
                                  b_down + 1 * HID, X1, 1,
                                  p_pool + HID, Pn + 1, Score);

    // 4) down level 2 (dense A2 via sparse spgemm); score fused into reduce
    k_topk_sort<<<1, 1024>>>(Score, 2048, 1024, P1, Vals, I1);
    k_spgemm2<<<1024, 256>>>(A1cols, A1vals, A1cnt, P1, I1, A2, D2, 1024);
    hW(X1, W_down + 2 * HID * HID, 1024, 4, D2, P1, Vals, nullptr, nullptr, T1, T2);
    at2(A2, T2, T1, 1024, 8, D2, b_down + 2 * HID, X2, 1,
        p_pool + 2 * HID, Pn + 2, Score);

    // 5) down level 3 (dense augment from A2)
    k_topk_sort<<<1, 1024>>>(Score, 1024, 512, P2, Vals, I2);
    {
        size_t t = (size_t)1024 * 512;
        k_gather_cols<<<(unsigned)((t + 255) / 256), 256>>>(A2, P2, Qb, 512, 1024);
        dim3 gg(512 / 64, 512 / 64, 4);
        k_gemm_aug<<<gg, 256>>>(A2, P2, Qb, g_split, 512, 1024, 256);
        k_reduce_dis<<<512, 256>>>(g_split, 4, 512, A3, D3);
    }
    hW(X2, W_down + 3 * HID * HID, 512, 8, D3, P2, Vals, nullptr, nullptr, T1, T2);
    at2(A3, T2, T1, 512, 16, D3, b_down + 3 * HID, X3, 1,
        p_pool + 3 * HID, Pn + 3, Score);

    // 6) down level 4 (dense augment from A3)
    k_topk_sort<<<1, 1024>>>(Score, 512, 256, P3, Vals, I3);
    {
        size_t t = (size_t)512 * 256;
        k_gather_cols<<<(unsigned)((t + 255) / 256), 256>>>(A3, P3, Qb, 256, 512);
        dim3 gg(256 / 64, 256 / 64, 16);
        k_gemm_aug<<<gg, 256>>>(A3, P3, Qb, g_split, 256, 512, 32);
        k_reduce_dis<<<256, 256>>>(g_split, 16, 256, A4, D4);
    }
    hW(X3, W_down + 4 * HID * HID, 256, 8, D4, P3, Vals, nullptr, nullptr, T1, T2);
    at2(A4, T2, T1, 256, 16, D4, b_down + 4 * HID, Hb, 1, nullptr, nullptr, nullptr);

    // 7) up path (unpool fused into hW A-loads)
    // j = 3 (n = 512)
    hW(Hb, W_up, 512, 8, D3, nullptr, nullptr, X3, I3, T1, T2);
    at2(A3, T2, T1, 512, 16, D3, b_up, Hb, 1, nullptr, nullptr, nullptr);
    // j = 2 (n = 1024)
    hW(Hb, W_up + 1 * HID * HID, 1024, 4, D2, nullptr, nullptr, X2, I2, T1, T2);
    at2(A2, T2, T1, 1024, 8, D2, b_up + 1 * HID, Hb, 1, nullptr, nullptr, nullptr);
    // j = 1 (n = 2048, sparse A1)
    hW(Hb, W_up + 2 * HID * HID, 2048, 1, D1, nullptr, nullptr, X1, I1, T1, T2);
    k_spmm1_ep<<<2048 / 8, 256>>>(A1cols, A1vals, A1cnt, T2, T1, D1,
                                  b_up + 2 * HID, Hb, 1,
                                  nullptr, nullptr, nullptr);
    // j = 0 (n = 4096, final conv HID->1 on CSR A0)
    k_hw_out_uf<<<N0, HID>>>(X0, Hb, I0, W_out, D0, HWo, Gv);
    k_final_sp<<<(N0 + 127) / 128, 128>>>(Rp, ColA, Gv, HWo, D0, b_out, out);
}

// round 15
// speedup vs baseline: 1.0493x; 1.0493x over previous
#include <cuda_runtime.h>
#include <math.h>
#include <stdint.h>

#define N0    4096
#define EDGES 65536
#define HID   128

// ---------------- device global scratch ----------------
__device__ int   dA1cols[(size_t)2048 * 2048];
__device__ float dA1vals[(size_t)2048 * 2048];
__device__ int   dA1cnt[2048];
__device__ float dA2[(size_t)1024 * 1024];
__device__ float dA3[(size_t)512 * 512];
__device__ float dA4[(size_t)256 * 256];
__device__ float dSplit[1 << 20];              // split-K partials (4 MB)
__device__ float dQbuf[(size_t)1024 * 512];
__device__ float dX0[N0 * HID];
__device__ float dX1[2048 * HID];
__device__ float dX2[1024 * HID];
__device__ float dX3[512 * HID];
__device__ float dHa[N0 * HID];
__device__ float dHb[N0 * HID];
__device__ float dT1[N0 * HID];
__device__ float dT2[N0 * HID];
__device__ float dScore[N0];
__device__ float dValsArr[N0];
__device__ float dHWo[N0];
__device__ float dGv[N0];
__device__ float dPn[4];
__device__ int   dPerm0[2048];
__device__ int   dPerm1[1024];
__device__ int   dPerm2[512];
__device__ int   dPerm3[256];
__device__ int   dInv0[4096];
__device__ int   dInv1[2048];
__device__ int   dInv2[1024];
__device__ int   dInv3[512];
__device__ float dDis0[4096];
__device__ float dDis1[2048];
__device__ float dDis2[1024];
__device__ float dDis3[512];
__device__ float dDis4[256];
__device__ int   dRp[N0 + 1];
__device__ int   dColA[EDGES];
__device__ int   dCnt[N0];
__device__ int   dCur[N0];

// ---------------- packed f32x2 FMA ----------------
__device__ __forceinline__ void ffma2(unsigned long long& d, unsigned long long a,
                                      unsigned long long b) {
    asm("fma.rn.f32x2 %0, %1, %2, %0;" : "+l"(d) : "l"(a), "l"(b));
}

// ---------------- setup kernels ----------------

__global__ void k_zero2(int* a, int* b, int n) {
    int i = blockIdx.x * blockDim.x + threadIdx.x;
    if (i < n) { a[i] = 0; b[i] = 0; }
}

__global__ void k_count(const int* __restrict__ ei, int* __restrict__ cnt) {
    int e = blockIdx.x * blockDim.x + threadIdx.x;
    if (e < EDGES) atomicAdd(&cnt[ei[EDGES + e]], 1);
}

// warp-based exclusive scan of 4096 counts + fused dis0 + fused p-norms
__global__ void k_scan_dis(const int* __restrict__ cnt, int* __restrict__ rp,
                           float* __restrict__ dis,
                           const float* __restrict__ p_pool, float* __restrict__ pn) {
    __shared__ int wsum[32];
    int tid = threadIdx.x;           // 1024 threads
    int base = tid * 4;
    int4 c = *(const int4*)(cnt + base);
    int s1 = c.x, s2 = s1 + c.y, s3 = s2 + c.z, s4 = s3 + c.w;
    int lane = tid & 31, w = tid >> 5;
    int v = s4;
#pragma unroll
    for (int o = 1; o < 32; o <<= 1) {
        int nv = __shfl_up_sync(~0u, v, o);
        if (lane >= o) v += nv;
    }
    if (lane == 31) wsum[w] = v;
    __syncthreads();
    if (w == 0) {
        int x = wsum[lane];
#pragma unroll
        for (int o = 1; o < 32; o <<= 1) {
            int nv = __shfl_up_sync(~0u, x, o);
            if (lane >= o) x += nv;
        }
        wsum[lane] = x;
    }
    __syncthreads();
    int warpBase = (w > 0) ? wsum[w - 1] : 0;
    int tbase = warpBase + v - s4;
    rp[base + 1] = tbase + s1;
    rp[base + 2] = tbase + s2;
    rp[base + 3] = tbase + s3;
    rp[base + 4] = tbase + s4;
    if (tid == 0) rp[0] = 0;
    dis[base]     = rsqrtf((float)c.x + 2.0f);
    dis[base + 1] = rsqrtf((float)c.y + 2.0f);
    dis[base + 2] = rsqrtf((float)c.z + 2.0f);
    dis[base + 3] = rsqrtf((float)c.w + 2.0f);
    if (w < 4) {
        float s = 0.0f;
        for (int cc = lane; cc < HID; cc += 32) {
            float pv = p_pool[w * HID + cc];
            s += pv * pv;
        }
#pragma unroll
        for (int o = 16; o; o >>= 1) s += __shfl_down_sync(0xffffffffu, s, o);
        if (lane == 0) pn[w] = sqrtf(s);
    }
}

__global__ void k_fill(const int* __restrict__ ei, const int* __restrict__ rp,
                       int* __restrict__ cur, int* __restrict__ colA) {
    int e = blockIdx.x * blockDim.x + threadIdx.x;
    if (e < EDGES) {
        int s = ei[e], d = ei[EDGES + e];
        int pos = rp[d] + atomicAdd(&cur[d], 1);
        colA[pos] = s;
    }
}

// ---------------- sparse augment ----------------

// Level-1: A1 = offdiag((B@B)[perm,perm]) sparse; also writes dis1.
__global__ void k_spgemm1(const int* __restrict__ rp, const int* __restrict__ colA,
                          const int* __restrict__ perm, const int* __restrict__ inv,
                          int* __restrict__ oCols, float* __restrict__ oVals,
                          int* __restrict__ oCnt, float* __restrict__ dis1) {
    __shared__ float accs[2048];
    __shared__ int   tpre[256];
    __shared__ float fsum[256];
    int r = blockIdx.x;
    int pr = perm[r];
    for (int i = threadIdx.x; i < 2048; i += blockDim.x) accs[i] = 0.0f;
    __syncthreads();
    int s = rp[pr], e = rp[pr + 1];
    int outerCnt = (e - s) + 1;
    for (int oi = threadIdx.x; oi < outerCnt; oi += blockDim.x) {
        int m = (oi < e - s) ? colA[s + oi] : pr;
        if (oi < e - s && m == pr) continue;
        int s2 = rp[m], e2 = rp[m + 1];
        for (int t = s2; t < e2; t++) {
            int j = colA[t];
            if (j == m) continue;
            int c = inv[j];
            if (c >= 0) atomicAdd(&accs[c], 1.0f);
        }
        int cm = inv[m];
        if (cm >= 0) atomicAdd(&accs[cm], 1.0f);
    }
    __syncthreads();
    int base = threadIdx.x * 8;
    int lc = 0;
    float ls = 0.0f;
#pragma unroll
    for (int j = 0; j < 8; j++) {
        int c = base + j;
        float v = accs[c];
        if (c != r && v != 0.0f) { lc++; ls += v; }
    }
    tpre[threadIdx.x] = lc;
    fsum[threadIdx.x] = ls;
    __syncthreads();
    for (int off = 1; off < 256; off <<= 1) {
        int v = (threadIdx.x >= off) ? tpre[threadIdx.x - off] : 0;
        float f = (threadIdx.x >= off) ? fsum[threadIdx.x - off] : 0.0f;
        __syncthreads();
        tpre[threadIdx.x] += v;
        fsum[threadIdx.x] += f;
        __syncthreads();
    }
    int pos = tpre[threadIdx.x] - lc;
#pragma unroll
    for (int j = 0; j < 8; j++) {
        int c = base + j;
        float v = accs[c];
        if (c != r && v != 0.0f) {
            oCols[(size_t)r * 2048 + pos] = c;
            oVals[(size_t)r * 2048 + pos] = v;
            pos++;
        }
    }
    if (threadIdx.x == 255) {
        oCnt[r] = tpre[255];
        dis1[r] = rsqrtf(fsum[255] + 2.0f);
    }
}

// Level-2: A2 dense = offdiag((B1@B1)[perm,perm]); fused dis2.
__global__ void k_spgemm2(const int* __restrict__ oCols, const float* __restrict__ oVals,
                          const int* __restrict__ oCnt,
                          const int* __restrict__ perm, const int* __restrict__ invg,
                          float* __restrict__ A2, float* __restrict__ dis2, int kOut) {
    __shared__ float accs[1024];
    __shared__ int   sinv[2048];
    __shared__ float red[8];
    int r = blockIdx.x;
    int pr = perm[r];
    int tid = threadIdx.x;
    for (int i = tid; i < kOut; i += 256) accs[i] = 0.0f;
    for (int i = tid; i < 2048; i += 256) sinv[i] = invg[i];
    __syncthreads();
    int cnt = oCnt[pr];
    const int*   cols = oCols + (size_t)pr * 2048;
    const float* vals = oVals + (size_t)pr * 2048;
    int lane = tid & 31, w = tid >> 5;
    for (int oi = w; oi <= cnt; oi += 8) {
        int m; float vOut;
        if (oi < cnt) { m = cols[oi]; vOut = vals[oi]; }
        else          { m = pr;       vOut = 1.0f; }
        int cnt2 = oCnt[m];
        const int*   cols2 = oCols + (size_t)m * 2048;
        const float* vals2 = oVals + (size_t)m * 2048;
        for (int t2 = lane; t2 < cnt2; t2 += 32) {
            int c = sinv[cols2[t2]];
            if (c >= 0) atomicAdd(&accs[c], vOut * vals2[t2]);
        }
        if (lane == 0) {
            int cm = sinv[m];
            if (cm >= 0) atomicAdd(&accs[cm], vOut);
        }
    }
    __syncthreads();
    float s = 0.0f;
    for (int c = tid; c < kOut; c += 256) {
        float v = (c == r) ? 0.0f : accs[c];
        s += v;
        A2[(size_t)r * kOut + c] = v;
    }
#pragma unroll
    for (int off = 16; off; off >>= 1) s += __shfl_down_sync(0xffffffffu, s, off);
    if (lane == 0) red[w] = s;
    __syncthreads();
    if (tid == 0) {
        float tot = 0.0f;
#pragma unroll
        for (int i = 0; i < 8; i++) tot += red[i];
        dis2[r] = rsqrtf(tot + 2.0f);
    }
}

// ---------------- sparse GCN propagation (warp-per-row, float4, fused score) ----------------

__global__ void k_spmm0_ep(const int* __restrict__ rp, const int* __restrict__ colA,
                           const float* __restrict__ T2, const float* __restrict__ T1,
                           const float* __restrict__ dis, const float* __restrict__ b,
                           float* __restrict__ out, int relu,
                           const float* __restrict__ p, const float* __restrict__ pnP,
                           float* __restrict__ score) {
    int w = threadIdx.x >> 5, lane = threadIdx.x & 31;
    int i = blockIdx.x * 8 + w;
    int s = rp[i], e = rp[i + 1];
    float4 acc = make_float4(0.f, 0.f, 0.f, 0.f);
    for (int t = s; t < e; t++) {
        int c = colA[t];
        float4 tv = *(const float4*)(T2 + (size_t)c * HID + lane * 4);
        acc.x += tv.x; acc.y += tv.y; acc.z += tv.z; acc.w += tv.w;
    }
    float di = dis[i];
    float4 t1 = *(const float4*)(T1 + (size_t)i * HID + lane * 4);
    float4 bv = *(const float4*)(b + lane * 4);
    float4 o;
    o.x = di * (acc.x + 2.0f * di * t1.x) + bv.x;
    o.y = di * (acc.y + 2.0f * di * t1.y) + bv.y;
    o.z = di * (acc.z + 2.0f * di * t1.z) + bv.z;
    o.w = di * (acc.w + 2.0f * di * t1.w) + bv.w;
    if (relu) {
        o.x = fmaxf(o.x, 0.f); o.y = fmaxf(o.y, 0.f);
        o.z = fmaxf(o.z, 0.f); o.w = fmaxf(o.w, 0.f);
    }
    *(float4*)(out + (size_t)i * HID + lane * 4) = o;
    if (p) {
        float4 pv = *(const float4*)(p + lane * 4);
        float d = o.x * pv.x + o.y * pv.y + o.z * pv.z + o.w * pv.w;
#pragma unroll
        for (int off = 16; off; off >>= 1) d += __shfl_down_sync(0xffffffffu, d, off);
        if (lane == 0) score[i] = d / pnP[0];
    }
}

__global__ void k_spmm1_ep(const int* __restrict__ oCols, const float* __restrict__ oVals,
                           const int* __restrict__ oCnt,
                           const float* __restrict__ T2, const float* __restrict__ T1,
                           const float* __restrict__ dis, const float* __restrict__ b,
                           float* __restrict__ out, int relu,
                           const float* __restrict__ p, const float* __restrict__ pnP,
                           float* __restrict__ score) {
    int w = threadIdx.x >> 5, lane = threadIdx.x & 31;
    int i = blockIdx.x * 8 + w;
    int cnt = oCnt[i];
    const int*   cols = oCols + (size_t)i * 2048;
    const float* vals = oVals + (size_t)i * 2048;
    float4 acc = make_float4(0.f, 0.f, 0.f, 0.f);
    for (int t = 0; t < cnt; t++) {
        int c = cols[t];
        float v = vals[t];
        float4 tv = *(const float4*)(T2 + (size_t)c * HID + lane * 4);
        acc.x += v * tv.x; acc.y += v * tv.y; acc.z += v * tv.z; acc.w += v * tv.w;
    }
    float di = dis[i];
    float4 t1 = *(const float4*)(T1 + (size_t)i * HID + lane * 4);
    float4 bv = *(const float4*)(b + lane * 4);
    float4 o;
    o.x = di * (acc.x + 2.0f * di * t1.x) + bv.x;
    o.y = di * (acc.y + 2.0f * di * t1.y) + bv.y;
    o.z = di * (acc.z + 2.0f * di * t1.z) + bv.z;
    o.w = di * (acc.w + 2.0f * di * t1.w) + bv.w;
    if (relu) {
        o.x = fmaxf(o.x, 0.f); o.y = fmaxf(o.y, 0.f);
        o.z = fmaxf(o.z, 0.f); o.w = fmaxf(o.w, 0.f);
    }
    *(float4*)(out + (size_t)i * HID + lane * 4) = o;
    if (p) {
        float4 pv = *(const float4*)(p + lane * 4);
        float d = o.x * pv.x + o.y * pv.y + o.z * pv.z + o.w * pv.w;
#pragma unroll
        for (int off = 16; off; off >>= 1) d += __shfl_down_sync(0xffffffffu, d, off);
        if (lane == 0) score[i] = d / pnP[0];
    }
}

// ---------------- dense kernels ----------------

__global__ void k_encoder(const float* __restrict__ x, const float* __restrict__ W,
                          const float* __restrict__ b, float* __restrict__ h) {
    int i = blockIdx.x;
    int c = threadIdx.x;
    float acc = b[c];
#pragma unroll
    for (int k = 0; k < 16; k++) acc += x[i * 16 + k] * W[k * HID + c];
    h[i * HID + c] = acc;
}

// Split-K SGEMM (packed f32x2) with A-row virtualization (pool/unpool fused).
// If T1o != null (requires gridDim.z == 1): direct epilogue T1o=acc, T2o=dis*acc.
__global__ void k_gemm_sk(const float* __restrict__ A, const float* __restrict__ B,
                          float* __restrict__ P, int M, int N, int K, int Kc,
                          const int* __restrict__ perm, const float* __restrict__ vals,
                          const float* __restrict__ Xs, const int* __restrict__ inv,
                          float* __restrict__ T1o, float* __restrict__ T2o,
                          const float* __restrict__ disEp) {
    __shared__ float Asd[16][132];
    __shared__ float Bs[16][64];
    int t = threadIdx.x;
    int m0 = blockIdx.y * 64, n0 = blockIdx.x * 64;
    int kBeg = blockIdx.z * Kc;
    int ar = t >> 2, ac = (t & 3) << 2;
    int bk = t >> 4, bn = (t & 15) << 2;
    int tm = (t >> 4) << 2, tn = (t & 15) << 2;
    int row = m0 + ar;

    const float* Aptr;
    const float* Xptr = nullptr;
    float gate = 1.0f;
    bool haveA = true;
    if (perm) {
        Aptr = A + (size_t)perm[row] * K + kBeg + ac;
        gate = tanhf(vals[row]);
    } else if (Xs) {
        int iv = inv[row];
        Xptr = Xs + (size_t)row * K + kBeg + ac;
        haveA = (iv >= 0);
        Aptr = haveA ? A + (size_t)iv * K + kBeg + ac : Xptr;
    } else {
        Aptr = A + (size_t)row * K + kBeg + ac;
    }

    unsigned long long acc[4][2];
#pragma unroll
    for (int a = 0; a < 4; a++) { acc[a][0] = 0ull; acc[a][1] = 0ull; }

    const float* Bptr = B + (size_t)(kBeg + bk) * N + n0 + bn;

    auto loadA = [&](int k0) -> float4 {
        float4 v = *(const float4*)(Aptr + k0);
        if (Xs) {
            if (haveA) {
                float4 xv = *(const float4*)(Xptr + k0);
                v.x += xv.x; v.y += xv.y; v.z += xv.z; v.w += xv.w;
            }
        } else if (perm) {
            v.x *= gate; v.y *= gate; v.z *= gate; v.w *= gate;
        }
        return v;
    };

    float4 av = loadA(0);
    float4 bv = *(const float4*)Bptr;
    for (int k0 = 0; k0 < Kc; k0 += 16) {
        *(float2*)&Asd[ac + 0][2 * ar] = make_float2(av.x, av.x);
        *(float2*)&Asd[ac + 1][2 * ar] = make_float2(av.y, av.y);
        *(float2*)&Asd[ac + 2][2 * ar] = make_float2(av.z, av.z);
        *(float2*)&Asd[ac + 3][2 * ar] = make_float2(av.w, av.w);
        *(float4*)&Bs[bk][bn] = bv;
        __syncthreads();
        if (k0 + 16 < Kc) {
            av = loadA(k0 + 16);
            bv = *(const float4*)(Bptr + (size_t)(k0 + 16) * N);
        }
#pragma unroll
        for (int kk = 0; kk < 16; kk++) {
            ulonglong2 a01 = *(const ulonglong2*)&Asd[kk][2 * tm];
            ulonglong2 a23 = *(const ulonglong2*)&Asd[kk][2 * tm + 4];
            ulonglong2 b01 = *(const ulonglong2*)&Bs[kk][tn];
            ffma2(acc[0][0], a01.x, b01.x); ffma2(acc[0][1], a01.x, b01.y);
            ffma2(acc[1][0], a01.y, b01.x); ffma2(acc[1][1], a01.y, b01.y);
            ffma2(acc[2][0], a23.x, b01.x); ffma2(acc[2][1], a23.x, b01.y);
            ffma2(acc[3][0], a23.y, b01.x); ffma2(acc[3][1], a23.y, b01.y);
        }
        __syncthreads();
    }
    if (T1o) {
#pragma unroll
        for (int a = 0; a < 4; a++) {
            int gm = m0 + tm + a;
            float di = disEp[gm];
            float4 o;
            o.x = __uint_as_float((unsigned)acc[a][0]);
            o.y = __uint_as_float((unsigned)(acc[a][0] >> 32));
            o.z = __uint_as_float((unsigned)acc[a][1]);
            o.w = __uint_as_float((unsigned)(acc[a][1] >> 32));
            *(float4*)&T1o[(size_t)gm * N + n0 + tn] = o;
            float4 o2 = make_float4(di * o.x, di * o.y, di * o.z, di * o.w);
            *(float4*)&T2o[(size_t)gm * N + n0 + tn] = o2;
        }
        return;
    }
    float* Pp = P + (size_t)blockIdx.z * M * N;
#pragma unroll
    for (int a = 0; a < 4; a++) {
        int gm = m0 + tm + a;
        float4 o;
        o.x = __uint_as_float((unsigned)acc[a][0]);
        o.y = __uint_as_float((unsigned)(acc[a][0] >> 32));
        o.z = __uint_as_float((unsigned)acc[a][1]);
        o.w = __uint_as_float((unsigned)(acc[a][1] >> 32));
        *(float4*)&Pp[(size_t)gm * N + n0 + tn] = o;
    }
}

// Augment GEMM: A row-gathered: A[r,c] = B1[perm[r], c]
__global__ void k_gemm_aug(const float* __restrict__ Aprev, const int* __restrict__ perm,
                           const float* __restrict__ B, float* __restrict__ P,
                           int Mk, int K, int Kc) {
    __shared__ float Asd[16][132];
    __shared__ float Bs[16][64];
    int t = threadIdx.x;
    int m0 = blockIdx.y * 64, n0 = blockIdx.x * 64;
    int kBeg = blockIdx.z * Kc;
    int ar = t >> 2, ac = (t & 3) << 2;
    int bk = t >> 4, bn = (t & 15) << 2;
    int tm = (t >> 4) << 2, tn = (t & 15) << 2;
    int pr = perm[m0 + ar];

    unsigned long long acc[4][2];
#pragma unroll
    for (int a = 0; a < 4; a++) { acc[a][0] = 0ull; acc[a][1] = 0ull; }

    const float* Aptr = Aprev + (size_t)pr * K + kBeg + ac;
    const float* Bptr = B + (size_t)(kBeg + bk) * Mk + n0 + bn;

    auto loadA = [&](int k0) -> float4 {
        float4 v = *(const float4*)(Aptr + k0);
        int cbase = kBeg + k0 + ac;
        if (pr >= cbase && pr < cbase + 4) ((float*)&v)[pr - cbase] = 1.0f;
        return v;
    };

    float4 av = loadA(0);
    float4 bv = *(const float4*)Bptr;
    for (int k0 = 0; k0 < Kc; k0 += 16) {
        *(float2*)&Asd[ac + 0][2 * ar] = make_float2(av.x, av.x);
        *(float2*)&Asd[ac + 1][2 * ar] = make_float2(av.y, av.y);
        *(float2*)&Asd[ac + 2][2 * ar] = make_float2(av.z, av.z);
        *(float2*)&Asd[ac + 3][2 * ar] = make_float2(av.w, av.w);
        *(float4*)&Bs[bk][bn] = bv;
        __syncthreads();
        if (k0 + 16 < Kc) {
            av = loadA(k0 + 16);
            bv = *(const float4*)(Bptr + (size_t)(k0 + 16) * Mk);
        }
#pragma unroll
        for (int kk = 0; kk < 16; kk++) {
            ulonglong2 a01 = *(const ulonglong2*)&Asd[kk][2 * tm];
            ulonglong2 a23 = *(const ulonglong2*)&Asd[kk][2 * tm + 4];
            ulonglong2 b01 = *(const ulonglong2*)&Bs[kk][tn];
            ffma2(acc[0][0], a01.x, b01.x); ffma2(acc[0][1], a01.x, b01.y);
            ffma2(acc[1][0], a01.y, b01.x); ffma2(acc[1][1], a01.y, b01.y);
            ffma2(acc[2][0], a23.x, b01.x); ffma2(acc[2][1], a23.x, b01.y);
            ffma2(acc[3][0], a23.y, b01.x); ffma2(acc[3][1], a23.y, b01.y);
        }
        __syncthreads();
    }
    float* Pp = P + (size_t)blockIdx.z * Mk * Mk;
#pragma unroll
    for (int a = 0; a < 4; a++) {
        int gm = m0 + tm + a;
        float4 o;
        o.x = __uint_as_float((unsigned)acc[a][0]);
        o.y = __uint_as_float((unsigned)(acc[a][0] >> 32));
        o.z = __uint_as_float((unsigned)acc[a][1]);
        o.w = __uint_as_float((unsigned)(acc[a][1] >> 32));
        *(float4*)&Pp[(size_t)gm * Mk + n0 + tn] = o;
    }
}

// Reduce split-K partials + fused epilogue.
// mode 0: C = sum (T1); C2 = dis[row]*sum (T2)
// mode 2: C = [relu]( dis*(sum + 2*dis*C2in) + bias ); optional fused score.
__global__ void k_reduce(const float* __restrict__ P, int S, int M, int N, int mode,
                         const float* __restrict__ dis, const float* __restrict__ bias,
                         float* __restrict__ C, float* __restrict__ C2, int relu,
                         const float* __restrict__ p, const float* __restrict__ pnP,
                         float* __restrict__ scoreP) {
    int tid = threadIdx.x;
    int idx = blockIdx.x * blockDim.x + tid;
    int total = M * N;
    if (idx >= total) return;
    float s = 0.0f;
    for (int z = 0; z < S; z++) s += P[(size_t)z * total + idx];
    int gm = idx / N;
    int gn = idx - gm * N;
    if (mode == 0) {
        C[idx] = s;
        C2[idx] = dis[gm] * s;
    } else {
        float di = dis[gm];
        float v = di * (s + 2.0f * di * C2[idx]) + bias[gn];
        if (relu) v = fmaxf(v, 0.0f);
        C[idx] = v;
        if (scoreP) {
            __shared__ float sm[256];
            sm[tid] = v * p[gn];
            __syncthreads();
            for (int o = 64; o > 0; o >>= 1) {
                if ((tid & 127) < o) sm[tid] += sm[tid + o];
                __syncthreads();
            }
            if ((tid & 127) == 0) scoreP[gm] = sm[tid] / pnP[0];
        }
    }
}

// Per-row reduce of augment partials: zero diag, write A, rowsum -> dis.
__global__ void k_reduce_dis(const float* __restrict__ P, int S, int k,
                             float* __restrict__ A, float* __restrict__ dis) {
    __shared__ float red[8];
    int r = blockIdx.x;
    int tid = threadIdx.x;
    float s = 0.0f;
    for (int c = tid; c < k; c += 256) {
        float v = 0.0f;
        for (int z = 0; z < S; z++) v += P[(size_t)z * k * k + (size_t)r * k + c];
        if (c == r) v = 0.0f;
        s += v;
        A[(size_t)r * k + c] = v;
    }
    int lane = tid & 31, w = tid >> 5;
#pragma unroll
    for (int off = 16; off; off >>= 1) s += __shfl_down_sync(0xffffffffu, s, off);
    if (lane == 0) red[w] = s;
    __syncthreads();
    if (tid == 0) {
        float tot = 0.0f;
#pragma unroll
        for (int i = 0; i < 8; i++) tot += red[i];
        dis[r] = rsqrtf(tot + 2.0f);
    }
}

// Q[m, c] = B1[m, perm[c]]  (column gather with diag patch)
__global__ void k_gather_cols(const float* __restrict__ A, const int* __restrict__ perm,
                              float* __restrict__ Q, int k, int n) {
    size_t idx = (size_t)blockIdx.x * blockDim.x + threadIdx.x;
    if (idx < (size_t)n * k) {
        int m = (int)(idx / k), c = (int)(idx % k);
        int pc = perm[c];
        float v = A[(size_t)m * n + pc];
        Q[idx] = (m == pc) ? 1.0f : v;
    }
}

// ---------------- pooling ----------------

// Packed-key bitonic sort with warp-fused tail (j<=16 via shfl_xor).
__global__ void k_topk_sort(const float* __restrict__ score, int n, int k,
                            int* __restrict__ perm, float* __restrict__ vals,
                            int* __restrict__ inv) {
    __shared__ unsigned long long key[4096];
    int tid = threadIdx.x;
    int lane = tid & 31, w = tid >> 5;
    int numWarps = blockDim.x >> 5;
    for (int i = tid; i < n; i += blockDim.x) {
        unsigned u = __float_as_uint(score[i]);
        u = (u & 0x80000000u) ? ~u : (u | 0x80000000u);
        key[i] = ((unsigned long long)u << 32) | (unsigned)(~i);
        inv[i] = -1;
    }
    __syncthreads();
    int half = n >> 1;
    for (int ksz = 2; ksz <= n; ksz <<= 1) {
        for (int j = ksz >> 1; j >= 32; j >>= 1) {
            for (int p = tid; p < half; p += blockDim.x) {
                int idx = ((p & ~(j - 1)) << 1) | (p & (j - 1));
                int ixj = idx | j;
                unsigned long long a = key[idx], b = key[ixj];
                bool dir = (idx & ksz) == 0;
                if (dir ? (b > a) : (a > b)) { key[idx] = b; key[ixj] = a; }
            }
            __syncthreads();
        }
        int jstart = (ksz >> 1 < 16) ? (ksz >> 1) : 16;
        for (int seg = w; seg < (n >> 5); seg += numWarps) {
            int idx = (seg << 5) | lane;
            unsigned long long v = key[idx];
            bool dir = (idx & ksz) == 0;
            for (int j = jstart; j >= 1; j >>= 1) {
                unsigned long long o = __shfl_xor_sync(0xffffffffu, v, j);
                bool lower = (lane & j) == 0;
                bool takeMax = (dir == lower);
                bool gt = (v > o);
                v = (takeMax == gt) ? v : o;
            }
            key[idx] = v;
        }
        __syncthreads();
    }
    for (int r = tid; r < k; r += blockDim.x) {
        int idx = (int)(~(unsigned)key[r]);
        perm[r] = idx;
        vals[r] = score[idx];
        inv[idx] = r;
    }
}

// ---------------- final conv (unpool fused) ----------------

__global__ void k_hw_out_uf(const float* __restrict__ X0, const float* __restrict__ h,
                            const int* __restrict__ inv, const float* __restrict__ Wout,
                            const float* __restrict__ dis, float* __restrict__ hw,
                            float* __restrict__ g) {
    int i = blockIdx.x;
    int c = threadIdx.x;
    float v = X0[i * HID + c];
    int r = inv[i];
    if (r >= 0) v += h[r * HID + c];
    __shared__ float sm[HID];
    sm[c] = v * Wout[c];
    __syncthreads();
    for (int o = 64; o > 0; o >>= 1) {
        if (c < o) sm[c] += sm[c + o];
        __syncthreads();
    }
    if (c == 0) { hw[i] = sm[0]; g[i] = dis[i] * sm[0]; }
}

__global__ void k_final_sp(const int* __restrict__ rp, const int* __restrict__ colA,
                           const float* __restrict__ g, const float* __restrict__ hw,
                           const float* __restrict__ dis, const float* __restrict__ b,
                           float* __restrict__ out) {
    int i = blockIdx.x * blockDim.x + threadIdx.x;
    if (i < N0) {
        float s = 0.0f;
        int a = rp[i], e = rp[i + 1];
        for (int t = a; t < e; t++) s += g[colA[t]];
        float di = dis[i];
        out[i] = di * (s + 2.0f * di * hw[i]) + b[0];
    }
}

// ---------------- host orchestration ----------------

static float* g_split = nullptr;

// h@W: direct S=1 epilogue when grid large (n>=2048); split-K otherwise.
static void hW(const float* Hin, const float* W, int n, int S, const float* dis,
               const int* perm, const float* vals, const float* Xs, const int* inv,
               float* T1, float* T2) {
    if (n >= 2048) {
        dim3 g(2, n / 64, 1);
        k_gemm_sk<<<g, 256>>>(Hin, W, nullptr, n, HID, HID, HID, perm, vals, Xs, inv,
                              T1, T2, dis);
    } else {
        dim3 g(2, n / 64, S);
        k_gemm_sk<<<g, 256>>>(Hin, W, g_split, n, HID, HID, HID / S, perm, vals, Xs, inv,
                              nullptr, nullptr, nullptr);
        int total = n * HID;
        k_reduce<<<total / 256, 256>>>(g_split, S, n, HID, 0, dis, nullptr,
                                       T1, T2, 0, nullptr, nullptr, nullptr);
    }
}

static void at2(const float* A, const float* T2, const float* T1, int n, int S,
                const float* dis, const float* bias, float* C, int relu,
                const float* p, const float* pnP, float* score) {
    dim3 g(2, n / 64, S);
    k_gemm_sk<<<g, 256>>>(A, T2, g_split, n, HID, n, n / S,
                          nullptr, nullptr, nullptr, nullptr,
                          nullptr, nullptr, nullptr);
    int total = n * HID;
    k_reduce<<<total / 256, 256>>>(g_split, S, n, HID, 2, dis, bias,
                                   C, (float*)T1, relu, p, pnP, score);
}

extern "C" void kernel_launch(void* const* d_in, const int* in_sizes, int n_in,
                              void* d_out, int out_size) {
    const float* x      = (const float*)d_in[0];
    const int*   ei     = (const int*)d_in[1];
    const float* W_enc  = (const float*)d_in[3];
    const float* b_enc  = (const float*)d_in[4];
    const float* W_down = (const float*)d_in[5];
    const float* b_down = (const float*)d_in[6];
    const float* W_up   = (const float*)d_in[7];
    const float* b_up   = (const float*)d_in[8];
    const float* W_out  = (const float*)d_in[9];
    const float* b_out  = (const float*)d_in[10];
    const float* p_pool = (const float*)d_in[11];
    float* out = (float*)d_out;

    float *A2, *A3, *A4, *Qb;
    float *X0, *X1, *X2, *X3, *Ha, *Hb, *T1, *T2;
    float *Score, *Vals, *HWo, *Gv, *Pn;
    float *A1vals;
    int *A1cols, *A1cnt;
    int *P0, *P1, *P2, *P3, *Rp, *ColA, *Cnt, *Cur;
    int *I0, *I1, *I2, *I3;
    float *D0, *D1, *D2, *D3, *D4;
    cudaGetSymbolAddress((void**)&A1cols, dA1cols);
    cudaGetSymbolAddress((void**)&A1vals, dA1vals);
    cudaGetSymbolAddress((void**)&A1cnt, dA1cnt);
    cudaGetSymbolAddress((void**)&A2, dA2);
    cudaGetSymbolAddress((void**)&A3, dA3);
    cudaGetSymbolAddress((void**)&A4, dA4);
    cudaGetSymbolAddress((void**)&g_split, dSplit);
    cudaGetSymbolAddress((void**)&Qb, dQbuf);
    cudaGetSymbolAddress((void**)&X0, dX0);
    cudaGetSymbolAddress((void**)&X1, dX1);
    cudaGetSymbolAddress((void**)&X2, dX2);
    cudaGetSymbolAddress((void**)&X3, dX3);
    cudaGetSymbolAddress((void**)&Ha, dHa);
    cudaGetSymbolAddress((void**)&Hb, dHb);
    cudaGetSymbolAddress((void**)&T1, dT1);
    cudaGetSymbolAddress((void**)&T2, dT2);
    cudaGetSymbolAddress((void**)&Score, dScore);
    cudaGetSymbolAddress((void**)&Vals, dValsArr);
    cudaGetSymbolAddress((void**)&HWo, dHWo);
    cudaGetSymbolAddress((void**)&Gv, dGv);
    cudaGetSymbolAddress((void**)&Pn, dPn);
    cudaGetSymbolAddress((void**)&P0, dPerm0);
    cudaGetSymbolAddress((void**)&P1, dPerm1);
    cudaGetSymbolAddress((void**)&P2, dPerm2);
    cudaGetSymbolAddress((void**)&P3, dPerm3);
    cudaGetSymbolAddress((void**)&I0, dInv0);
    cudaGetSymbolAddress((void**)&I1, dInv1);
    cudaGetSymbolAddress((void**)&I2, dInv2);
    cudaGetSymbolAddress((void**)&I3, dInv3);
    cudaGetSymbolAddress((void**)&D0, dDis0);
    cudaGetSymbolAddress((void**)&D1, dDis1);
    cudaGetSymbolAddress((void**)&D2, dDis2);
    cudaGetSymbolAddress((void**)&D3, dDis3);
    cudaGetSymbolAddress((void**)&D4, dDis4);
    cudaGetSymbolAddress((void**)&Rp, dRp);
    cudaGetSymbolAddress((void**)&ColA, dColA);
    cudaGetSymbolAddress((void**)&Cnt, dCnt);
    cudaGetSymbolAddress((void**)&Cur, dCur);

    // 1) node encoder + CSR of A0 (dis0 + p-norms fused into scan)
    k_encoder<<<N0, HID>>>(x, W_enc, b_enc, Ha);
    k_zero2<<<N0 / 256, 256>>>(Cnt, Cur, N0);
    k_count<<<EDGES / 256, 256>>>(ei, Cnt);
    k_scan_dis<<<1, 1024>>>(Cnt, Rp, D0, p_pool, Pn);
    k_fill<<<EDGES / 256, 256>>>(ei, Rp, Cur, ColA);

    // 2) down conv 0 (sparse, direct-epilogue GEMM, score fused) -> X0, Score
    hW(Ha, W_down, N0, 1, D0, nullptr, nullptr, nullptr, nullptr, T1, T2);
    k_spmm0_ep<<<N0 / 8, 256>>>(Rp, ColA, T2, T1, D0, b_down, X0, 1,
                                p_pool, Pn, Score);

    // 3) down level 1 (sparse A1); pool fused into hW; score fused into spmm
    k_topk_sort<<<1, 1024>>>(Score, 4096, 2048, P0, Vals, I0);
    k_spgemm1<<<2048, 256>>>(Rp, ColA, P0, I0, A1cols, A1vals, A1cnt, D1);
    hW(X0, W_down + 1 * HID * HID, 2048, 1, D1, P0, Vals, nullptr, nullptr, T1, T2);
    k_spmm1_ep<<<2048 / 8, 256>>>(A1cols, A1vals, A1cnt, T2, T1, D1,
                                  b_down + 1 * HID, X1, 1,
                                  p_pool + HID, Pn + 1, Score);

    // 4) down level 2 (dense A2 via sparse spgemm); score fused into reduce
    k_topk_sort<<<1, 1024>>>(Score, 2048, 1024, P1, Vals, I1);
    k_spgemm2<<<1024, 256>>>(A1cols, A1vals, A1cnt, P1, I1, A2, D2, 1024);
    hW(X1, W_down + 2 * HID * HID, 1024, 4, D2, P1, Vals, nullptr, nullptr, T1, T2);
    at2(A2, T2, T1, 1024, 8, D2, b_down + 2 * HID, X2, 1,
        p_pool + 2 * HID, Pn + 2, Score);

    // 5) down level 3 (dense augment from A2)
    k_topk_sort<<<1, 1024>>>(Score, 1024, 512, P2, Vals, I2);
    {
        size_t t = (size_t)1024 * 512;
        k_gather_cols<<<(unsigned)((t + 255) / 256), 256>>>(A2, P2, Qb, 512, 1024);
        dim3 gg(512 / 64, 512 / 64, 4);
        k_gemm_aug<<<gg, 256>>>(A2, P2, Qb, g_split, 512, 1024, 256);
        k_reduce_dis<<<512, 256>>>(g_split, 4, 512, A3, D3);
    }
    hW(X2, W_down + 3 * HID * HID, 512, 8, D3, P2, Vals, nullptr, nullptr, T1, T2);
    at2(A3, T2, T1, 512, 16, D3, b_down + 3 * HID, X3, 1,
        p_pool + 3 * HID, Pn + 3, Score);

    // 6) down level 4 (dense augment from A3)
    k_topk_sort<<<1, 1024>>>(Score, 512, 256, P3, Vals, I3);
    {
        size_t t = (size_t)512 * 256;
        k_gather_cols<<<(unsigned)((t + 255) / 256), 256>>>(A3, P3, Qb, 256, 512);
        dim3 gg(256 / 64, 256 / 64, 16);
        k_gemm_aug<<<gg, 256>>>(A3, P3, Qb, g_split, 256, 512, 32);
        k_reduce_dis<<<256, 256>>>(g_split, 16, 256, A4, D4);
    }
    hW(X3, W_down + 4 * HID * HID, 256, 8, D4, P3, Vals, nullptr, nullptr, T1, T2);
    at2(A4, T2, T1, 256, 16, D4, b_down + 4 * HID, Hb, 1, nullptr, nullptr, nullptr);

    // 7) up path (unpool fused into hW A-loads)
    // j = 3 (n = 512)
    hW(Hb, W_up, 512, 8, D3, nullptr, nullptr, X3, I3, T1, T2);
    at2(A3, T2, T1, 512, 16, D3, b_up, Hb, 1, nullptr, nullptr, nullptr);
    // j = 2 (n = 1024)
    hW(Hb, W_up + 1 * HID * HID, 1024, 4, D2, nullptr, nullptr, X2, I2, T1, T2);
    at2(A2, T2, T1, 1024, 8, D2, b_up + 1 * HID, Hb, 1, nullptr, nullptr, nullptr);
    // j = 1 (n = 2048, sparse A1)
    hW(Hb, W_up + 2 * HID * HID, 2048, 1, D1, nullptr, nullptr, X1, I1, T1, T2);
    k_spmm1_ep<<<2048 / 8, 256>>>(A1cols, A1vals, A1cnt, T2, T1, D1,
                                  b_up + 2 * HID, Hb, 1,
                                  nullptr, nullptr, nullptr);
    // j = 0 (n = 4096, final conv HID->1 on CSR A0)
    k_hw_out_uf<<<N0, HID>>>(X0, Hb, I0, W_out, D0, HWo, Gv);
    k_final_sp<<<(N0 + 127) / 128, 128>>>(Rp, ColA, Gv, HWo, D0, b_out, out);
}

// round 16
// speedup vs baseline: 1.0496x; 1.0002x over previous
#include <cuda_runtime.h>
#include <math.h>
#include <stdint.h>

#define N0    4096
#define EDGES 65536
#define HID   128

// ---------------- device global scratch ----------------
__device__ int   dA1cols[(size_t)2048 * 2048];
__device__ float dA1vals[(size_t)2048 * 2048];
__device__ int   dA1cnt[2048];
__device__ float dA2[(size_t)1024 * 1024];
__device__ float dA3[(size_t)512 * 512];
__device__ float dA4[(size_t)256 * 256];
__device__ float dSplit[1 << 20];              // split-K partials (4 MB)
__device__ float dQbuf[(size_t)1024 * 512];
__device__ float dX0[N0 * HID];
__device__ float dX1[2048 * HID];
__device__ float dX2[1024 * HID];
__device__ float dX3[512 * HID];
__device__ float dHa[N0 * HID];
__device__ float dHb[N0 * HID];
__device__ float dT1[N0 * HID];
__device__ float dT2[N0 * HID];
__device__ float dScore[N0];
__device__ float dValsArr[N0];
__device__ float dHWo[N0];
__device__ float dGv[N0];
__device__ float dPn[4];
__device__ int   dPerm0[2048];
__device__ int   dPerm1[1024];
__device__ int   dPerm2[512];
__device__ int   dPerm3[256];
__device__ int   dInv0[4096];
__device__ int   dInv1[2048];
__device__ int   dInv2[1024];
__device__ int   dInv3[512];
__device__ float dDis0[4096];
__device__ float dDis1[2048];
__device__ float dDis2[1024];
__device__ float dDis3[512];
__device__ float dDis4[256];
__device__ int   dRp[N0 + 1];
__device__ int   dColA[EDGES];
__device__ int   dCnt[N0];   // zero at load; self-cleaned by k_scan_dis each call
__device__ int   dCur[N0];   // zero at load; zeroed by k_scan_dis before k_fill

// ---------------- packed f32x2 FMA ----------------
__device__ __forceinline__ void ffma2(unsigned long long& d, unsigned long long a,
                                      unsigned long long b) {
    asm("fma.rn.f32x2 %0, %1, %2, %0;" : "+l"(d) : "l"(a), "l"(b));
}

// ---------------- setup kernels ----------------

__global__ void k_count(const int* __restrict__ ei, int* __restrict__ cnt) {
    int e = blockIdx.x * blockDim.x + threadIdx.x;
    if (e < EDGES) atomicAdd(&cnt[ei[EDGES + e]], 1);
}

// warp-based exclusive scan of 4096 counts + fused dis0 + fused p-norms.
// Self-cleaning: zeroes cnt (after reading) and cur, so the next graph
// replay sees the same initial state without a separate zero kernel.
__global__ void k_scan_dis(int* __restrict__ cnt, int* __restrict__ cur,
                           int* __restrict__ rp, float* __restrict__ dis,
                           const float* __restrict__ p_pool, float* __restrict__ pn) {
    __shared__ int wsum[32];
    int tid = threadIdx.x;           // 1024 threads
    int base = tid * 4;
    int4 c = *(const int4*)(cnt + base);
    int4 z4 = make_int4(0, 0, 0, 0);
    *(int4*)(cnt + base) = z4;
    *(int4*)(cur + base) = z4;
    int s1 = c.x, s2 = s1 + c.y, s3 = s2 + c.z, s4 = s3 + c.w;
    int lane = tid & 31, w = tid >> 5;
    int v = s4;
#pragma unroll
    for (int o = 1; o < 32; o <<= 1) {
        int nv = __shfl_up_sync(~0u, v, o);
        if (lane >= o) v += nv;
    }
    if (lane == 31) wsum[w] = v;
    __syncthreads();
    if (w == 0) {
        int x = wsum[lane];
#pragma unroll
        for (int o = 1; o < 32; o <<= 1) {
            int nv = __shfl_up_sync(~0u, x, o);
            if (lane >= o) x += nv;
        }
        wsum[lane] = x;
    }
    __syncthreads();
    int warpBase = (w > 0) ? wsum[w - 1] : 0;
    int tbase = warpBase + v - s4;
    rp[base + 1] = tbase + s1;
    rp[base + 2] = tbase + s2;
    rp[base + 3] = tbase + s3;
    rp[base + 4] = tbase + s4;
    if (tid == 0) rp[0] = 0;
    dis[base]     = rsqrtf((float)c.x + 2.0f);
    dis[base + 1] = rsqrtf((float)c.y + 2.0f);
    dis[base + 2] = rsqrtf((float)c.z + 2.0f);
    dis[base + 3] = rsqrtf((float)c.w + 2.0f);
    if (w < 4) {
        float s = 0.0f;
        for (int cc = lane; cc < HID; cc += 32) {
            float pv = p_pool[w * HID + cc];
            s += pv * pv;
        }
#pragma unroll
        for (int o = 16; o; o >>= 1) s += __shfl_down_sync(0xffffffffu, s, o);
        if (lane == 0) pn[w] = sqrtf(s);
    }
}

__global__ void k_fill(const int* __restrict__ ei, const int* __restrict__ rp,
                       int* __restrict__ cur, int* __restrict__ colA) {
    int e = blockIdx.x * blockDim.x + threadIdx.x;
    if (e < EDGES) {
        int s = ei[e], d = ei[EDGES + e];
        int pos = rp[d] + atomicAdd(&cur[d], 1);
        colA[pos] = s;
    }
}

// ---------------- sparse augment ----------------

// Level-1: A1 = offdiag((B@B)[perm,perm]) sparse; also writes dis1.
__global__ void k_spgemm1(const int* __restrict__ rp, const int* __restrict__ colA,
                          const int* __restrict__ perm, const int* __restrict__ inv,
                          int* __restrict__ oCols, float* __restrict__ oVals,
                          int* __restrict__ oCnt, float* __restrict__ dis1) {
    __shared__ float accs[2048];
    __shared__ int   tpre[256];
    __shared__ float fsum[256];
    int r = blockIdx.x;
    int pr = perm[r];
    for (int i = threadIdx.x; i < 2048; i += blockDim.x) accs[i] = 0.0f;
    __syncthreads();
    int s = rp[pr], e = rp[pr + 1];
    int outerCnt = (e - s) + 1;
    for (int oi = threadIdx.x; oi < outerCnt; oi += blockDim.x) {
        int m = (oi < e - s) ? colA[s + oi] : pr;
        if (oi < e - s && m == pr) continue;
        int s2 = rp[m], e2 = rp[m + 1];
        for (int t = s2; t < e2; t++) {
            int j = colA[t];
            if (j == m) continue;
            int c = inv[j];
            if (c >= 0) atomicAdd(&accs[c], 1.0f);
        }
        int cm = inv[m];
        if (cm >= 0) atomicAdd(&accs[cm], 1.0f);
    }
    __syncthreads();
    int base = threadIdx.x * 8;
    int lc = 0;
    float ls = 0.0f;
#pragma unroll
    for (int j = 0; j < 8; j++) {
        int c = base + j;
        float v = accs[c];
        if (c != r && v != 0.0f) { lc++; ls += v; }
    }
    tpre[threadIdx.x] = lc;
    fsum[threadIdx.x] = ls;
    __syncthreads();
    for (int off = 1; off < 256; off <<= 1) {
        int v = (threadIdx.x >= off) ? tpre[threadIdx.x - off] : 0;
        float f = (threadIdx.x >= off) ? fsum[threadIdx.x - off] : 0.0f;
        __syncthreads();
        tpre[threadIdx.x] += v;
        fsum[threadIdx.x] += f;
        __syncthreads();
    }
    int pos = tpre[threadIdx.x] - lc;
#pragma unroll
    for (int j = 0; j < 8; j++) {
        int c = base + j;
        float v = accs[c];
        if (c != r && v != 0.0f) {
            oCols[(size_t)r * 2048 + pos] = c;
            oVals[(size_t)r * 2048 + pos] = v;
            pos++;
        }
    }
    if (threadIdx.x == 255) {
        oCnt[r] = tpre[255];
        dis1[r] = rsqrtf(fsum[255] + 2.0f);
    }
}

// Level-2: A2 dense = offdiag((B1@B1)[perm,perm]); fused dis2.
__global__ void k_spgemm2(const int* __restrict__ oCols, const float* __restrict__ oVals,
                          const int* __restrict__ oCnt,
                          const int* __restrict__ perm, const int* __restrict__ invg,
                          float* __restrict__ A2, float* __restrict__ dis2, int kOut) {
    __shared__ float accs[1024];
    __shared__ int   sinv[2048];
    __shared__ float red[8];
    int r = blockIdx.x;
    int pr = perm[r];
    int tid = threadIdx.x;
    for (int i = tid; i < kOut; i += 256) accs[i] = 0.0f;
    for (int i = tid; i < 2048; i += 256) sinv[i] = invg[i];
    __syncthreads();
    int cnt = oCnt[pr];
    const int*   cols = oCols + (size_t)pr * 2048;
    const float* vals = oVals + (size_t)pr * 2048;
    int lane = tid & 31, w = tid >> 5;
    for (int oi = w; oi <= cnt; oi += 8) {
        int m; float vOut;
        if (oi < cnt) { m = cols[oi]; vOut = vals[oi]; }
        else          { m = pr;       vOut = 1.0f; }
        int cnt2 = oCnt[m];
        const int*   cols2 = oCols + (size_t)m * 2048;
        const float* vals2 = oVals + (size_t)m * 2048;
        for (int t2 = lane; t2 < cnt2; t2 += 32) {
            int c = sinv[cols2[t2]];
            if (c >= 0) atomicAdd(&accs[c], vOut * vals2[t2]);
        }
        if (lane == 0) {
            int cm = sinv[m];
            if (cm >= 0) atomicAdd(&accs[cm], vOut);
        }
    }
    __syncthreads();
    float s = 0.0f;
    for (int c = tid; c < kOut; c += 256) {
        float v = (c == r) ? 0.0f : accs[c];
        s += v;
        A2[(size_t)r * kOut + c] = v;
    }
#pragma unroll
    for (int off = 16; off; off >>= 1) s += __shfl_down_sync(0xffffffffu, s, off);
    if (lane == 0) red[w] = s;
    __syncthreads();
    if (tid == 0) {
        float tot = 0.0f;
#pragma unroll
        for (int i = 0; i < 8; i++) tot += red[i];
        dis2[r] = rsqrtf(tot + 2.0f);
    }
}

// ---------------- sparse GCN propagation (warp-per-row, float4, fused score) ----------------

__global__ void k_spmm0_ep(const int* __restrict__ rp, const int* __restrict__ colA,
                           const float* __restrict__ T2, const float* __restrict__ T1,
                           const float* __restrict__ dis, const float* __restrict__ b,
                           float* __restrict__ out, int relu,
                           const float* __restrict__ p, const float* __restrict__ pnP,
                           float* __restrict__ score) {
    int w = threadIdx.x >> 5, lane = threadIdx.x & 31;
    int i = blockIdx.x * 8 + w;
    int s = rp[i], e = rp[i + 1];
    float4 acc = make_float4(0.f, 0.f, 0.f, 0.f);
    for (int t = s; t < e; t++) {
        int c = colA[t];
        float4 tv = *(const float4*)(T2 + (size_t)c * HID + lane * 4);
        acc.x += tv.x; acc.y += tv.y; acc.z += tv.z; acc.w += tv.w;
    }
    float di = dis[i];
    float4 t1 = *(const float4*)(T1 + (size_t)i * HID + lane * 4);
    float4 bv = *(const float4*)(b + lane * 4);
    float4 o;
    o.x = di * (acc.x + 2.0f * di * t1.x) + bv.x;
    o.y = di * (acc.y + 2.0f * di * t1.y) + bv.y;
    o.z = di * (acc.z + 2.0f * di * t1.z) + bv.z;
    o.w = di * (acc.w + 2.0f * di * t1.w) + bv.w;
    if (relu) {
        o.x = fmaxf(o.x, 0.f); o.y = fmaxf(o.y, 0.f);
        o.z = fmaxf(o.z, 0.f); o.w = fmaxf(o.w, 0.f);
    }
    *(float4*)(out + (size_t)i * HID + lane * 4) = o;
    if (p) {
        float4 pv = *(const float4*)(p + lane * 4);
        float d = o.x * pv.x + o.y * pv.y + o.z * pv.z + o.w * pv.w;
#pragma unroll
        for (int off = 16; off; off >>= 1) d += __shfl_down_sync(0xffffffffu, d, off);
        if (lane == 0) score[i] = d / pnP[0];
    }
}

__global__ void k_spmm1_ep(const int* __restrict__ oCols, const float* __restrict__ oVals,
                           const int* __restrict__ oCnt,
                           const float* __restrict__ T2, const float* __restrict__ T1,
                           const float* __restrict__ dis, const float* __restrict__ b,
                           float* __restrict__ out, int relu,
                           const float* __restrict__ p, const float* __restrict__ pnP,
                           float* __restrict__ score) {
    int w = threadIdx.x >> 5, lane = threadIdx.x & 31;
    int i = blockIdx.x * 8 + w;
    int cnt = oCnt[i];
    const int*   cols = oCols + (size_t)i * 2048;
    const float* vals = oVals + (size_t)i * 2048;
    float4 acc = make_float4(0.f, 0.f, 0.f, 0.f);
    for (int t = 0; t < cnt; t++) {
        int c = cols[t];
        float v = vals[t];
        float4 tv = *(const float4*)(T2 + (size_t)c * HID + lane * 4);
        acc.x += v * tv.x; acc.y += v * tv.y; acc.z += v * tv.z; acc.w += v * tv.w;
    }
    float di = dis[i];
    float4 t1 = *(const float4*)(T1 + (size_t)i * HID + lane * 4);
    float4 bv = *(const float4*)(b + lane * 4);
    float4 o;
    o.x = di * (acc.x + 2.0f * di * t1.x) + bv.x;
    o.y = di * (acc.y + 2.0f * di * t1.y) + bv.y;
    o.z = di * (acc.z + 2.0f * di * t1.z) + bv.z;
    o.w = di * (acc.w + 2.0f * di * t1.w) + bv.w;
    if (relu) {
        o.x = fmaxf(o.x, 0.f); o.y = fmaxf(o.y, 0.f);
        o.z = fmaxf(o.z, 0.f); o.w = fmaxf(o.w, 0.f);
    }
    *(float4*)(out + (size_t)i * HID + lane * 4) = o;
    if (p) {
        float4 pv = *(const float4*)(p + lane * 4);
        float d = o.x * pv.x + o.y * pv.y + o.z * pv.z + o.w * pv.w;
#pragma unroll
        for (int off = 16; off; off >>= 1) d += __shfl_down_sync(0xffffffffu, d, off);
        if (lane == 0) score[i] = d / pnP[0];
    }
}

// ---------------- dense kernels ----------------

__global__ void k_encoder(const float* __restrict__ x, const float* __restrict__ W,
                          const float* __restrict__ b, float* __restrict__ h) {
    int i = blockIdx.x;
    int c = threadIdx.x;
    float acc = b[c];
#pragma unroll
    for (int k = 0; k < 16; k++) acc += x[i * 16 + k] * W[k * HID + c];
    h[i * HID + c] = acc;
}

// Split-K SGEMM (packed f32x2) with A-row virtualization (pool/unpool fused).
// If T1o != null (requires gridDim.z == 1): direct epilogue T1o=acc, T2o=dis*acc.
__global__ void k_gemm_sk(const float* __restrict__ A, const float* __restrict__ B,
                          float* __restrict__ P, int M, int N, int K, int Kc,
                          const int* __restrict__ perm, const float* __restrict__ vals,
                          const float* __restrict__ Xs, const int* __restrict__ inv,
                          float* __restrict__ T1o, float* __restrict__ T2o,
                          const float* __restrict__ disEp) {
    __shared__ float Asd[16][132];
    __shared__ float Bs[16][64];
    int t = threadIdx.x;
    int m0 = blockIdx.y * 64, n0 = blockIdx.x * 64;
    int kBeg = blockIdx.z * Kc;
    int ar = t >> 2, ac = (t & 3) << 2;
    int bk = t >> 4, bn = (t & 15) << 2;
    int tm = (t >> 4) << 2, tn = (t & 15) << 2;
    int row = m0 + ar;

    const float* Aptr;
    const float* Xptr = nullptr;
    float gate = 1.0f;
    bool haveA = true;
    if (perm) {
        Aptr = A + (size_t)perm[row] * K + kBeg + ac;
        gate = tanhf(vals[row]);
    } else if (Xs) {
        int iv = inv[row];
        Xptr = Xs + (size_t)row * K + kBeg + ac;
        haveA = (iv >= 0);
        Aptr = haveA ? A + (size_t)iv * K + kBeg + ac : Xptr;
    } else {
        Aptr = A + (size_t)row * K + kBeg + ac;
    }

    unsigned long long acc[4][2];
#pragma unroll
    for (int a = 0; a < 4; a++) { acc[a][0] = 0ull; acc[a][1] = 0ull; }

    const float* Bptr = B + (size_t)(kBeg + bk) * N + n0 + bn;

    auto loadA = [&](int k0) -> float4 {
        float4 v = *(const float4*)(Aptr + k0);
        if (Xs) {
            if (haveA) {
                float4 xv = *(const float4*)(Xptr + k0);
                v.x += xv.x; v.y += xv.y; v.z += xv.z; v.w += xv.w;
            }
        } else if (perm) {
            v.x *= gate; v.y *= gate; v.z *= gate; v.w *= gate;
        }
        return v;
    };

    float4 av = loadA(0);
    float4 bv = *(const float4*)Bptr;
    for (int k0 = 0; k0 < Kc; k0 += 16) {
        *(float2*)&Asd[ac + 0][2 * ar] = make_float2(av.x, av.x);
        *(float2*)&Asd[ac + 1][2 * ar] = make_float2(av.y, av.y);
        *(float2*)&Asd[ac + 2][2 * ar] = make_float2(av.z, av.z);
        *(float2*)&Asd[ac + 3][2 * ar] = make_float2(av.w, av.w);
        *(float4*)&Bs[bk][bn] = bv;
        __syncthreads();
        if (k0 + 16 < Kc) {
            av = loadA(k0 + 16);
            bv = *(const float4*)(Bptr + (size_t)(k0 + 16) * N);
        }
#pragma unroll
        for (int kk = 0; kk < 16; kk++) {
            ulonglong2 a01 = *(const ulonglong2*)&Asd[kk][2 * tm];
            ulonglong2 a23 = *(const ulonglong2*)&Asd[kk][2 * tm + 4];
            ulonglong2 b01 = *(const ulonglong2*)&Bs[kk][tn];
            ffma2(acc[0][0], a01.x, b01.x); ffma2(acc[0][1], a01.x, b01.y);
            ffma2(acc[1][0], a01.y, b01.x); ffma2(acc[1][1], a01.y, b01.y);
            ffma2(acc[2][0], a23.x, b01.x); ffma2(acc[2][1], a23.x, b01.y);
            ffma2(acc[3][0], a23.y, b01.x); ffma2(acc[3][1], a23.y, b01.y);
        }
        __syncthreads();
    }
    if (T1o) {
#pragma unroll
        for (int a = 0; a < 4; a++) {
            int gm = m0 + tm + a;
            float di = disEp[gm];
            float4 o;
            o.x = __uint_as_float((unsigned)acc[a][0]);
            o.y = __uint_as_float((unsigned)(acc[a][0] >> 32));
            o.z = __uint_as_float((unsigned)acc[a][1]);
            o.w = __uint_as_float((unsigned)(acc[a][1] >> 32));
            *(float4*)&T1o[(size_t)gm * N + n0 + tn] = o;
            float4 o2 = make_float4(di * o.x, di * o.y, di * o.z, di * o.w);
            *(float4*)&T2o[(size_t)gm * N + n0 + tn] = o2;
        }
        return;
    }
    float* Pp = P + (size_t)blockIdx.z * M * N;
#pragma unroll
    for (int a = 0; a < 4; a++) {
        int gm = m0 + tm + a;
        float4 o;
        o.x = __uint_as_float((unsigned)acc[a][0]);
        o.y = __uint_as_float((unsigned)(acc[a][0] >> 32));
        o.z = __uint_as_float((unsigned)acc[a][1]);
        o.w = __uint_as_float((unsigned)(acc[a][1] >> 32));
        *(float4*)&Pp[(size_t)gm * N + n0 + tn] = o;
    }
}

// Augment GEMM: A row-gathered: A[r,c] = B1[perm[r], c]
__global__ void k_gemm_aug(const float* __restrict__ Aprev, const int* __restrict__ perm,
                           const float* __restrict__ B, float* __restrict__ P,
                           int Mk, int K, int Kc) {
    __shared__ float Asd[16][132];
    __shared__ float Bs[16][64];
    int t = threadIdx.x;
    int m0 = blockIdx.y * 64, n0 = blockIdx.x * 64;
    int kBeg = blockIdx.z * Kc;
    int ar = t >> 2, ac = (t & 3) << 2;
    int bk = t >> 4, bn = (t & 15) << 2;
    int tm = (t >> 4) << 2, tn = (t & 15) << 2;
    int pr = perm[m0 + ar];

    unsigned long long acc[4][2];
#pragma unroll
    for (int a = 0; a < 4; a++) { acc[a][0] = 0ull; acc[a][1] = 0ull; }

    const float* Aptr = Aprev + (size_t)pr * K + kBeg + ac;
    const float* Bptr = B + (size_t)(kBeg + bk) * Mk + n0 + bn;

    auto loadA = [&](int k0) -> float4 {
        float4 v = *(const float4*)(Aptr + k0);
        int cbase = kBeg + k0 + ac;
        if (pr >= cbase && pr < cbase + 4) ((float*)&v)[pr - cbase] = 1.0f;
        return v;
    };

    float4 av = loadA(0);
    float4 bv = *(const float4*)Bptr;
    for (int k0 = 0; k0 < Kc; k0 += 16) {
        *(float2*)&Asd[ac + 0][2 * ar] = make_float2(av.x, av.x);
        *(float2*)&Asd[ac + 1][2 * ar] = make_float2(av.y, av.y);
        *(float2*)&Asd[ac + 2][2 * ar] = make_float2(av.z, av.z);
        *(float2*)&Asd[ac + 3][2 * ar] = make_float2(av.w, av.w);
        *(float4*)&Bs[bk][bn] = bv;
        __syncthreads();
        if (k0 + 16 < Kc) {
            av = loadA(k0 + 16);
            bv = *(const float4*)(Bptr + (size_t)(k0 + 16) * Mk);
        }
#pragma unroll
        for (int kk = 0; kk < 16; kk++) {
            ulonglong2 a01 = *(const ulonglong2*)&Asd[kk][2 * tm];
            ulonglong2 a23 = *(const ulonglong2*)&Asd[kk][2 * tm + 4];
            ulonglong2 b01 = *(const ulonglong2*)&Bs[kk][tn];
            ffma2(acc[0][0], a01.x, b01.x); ffma2(acc[0][1], a01.x, b01.y);
            ffma2(acc[1][0], a01.y, b01.x); ffma2(acc[1][1], a01.y, b01.y);
            ffma2(acc[2][0], a23.x, b01.x); ffma2(acc[2][1], a23.x, b01.y);
            ffma2(acc[3][0], a23.y, b01.x); ffma2(acc[3][1], a23.y, b01.y);
        }
        __syncthreads();
    }
    float* Pp = P + (size_t)blockIdx.z * Mk * Mk;
#pragma unroll
    for (int a = 0; a < 4; a++) {
        int gm = m0 + tm + a;
        float4 o;
        o.x = __uint_as_float((unsigned)acc[a][0]);
        o.y = __uint_as_float((unsigned)(acc[a][0] >> 32));
        o.z = __uint_as_float((unsigned)acc[a][1]);
        o.w = __uint_as_float((unsigned)(acc[a][1] >> 32));
        *(float4*)&Pp[(size_t)gm * Mk + n0 + tn] = o;
    }
}

// Reduce split-K partials + fused epilogue.
// mode 0: C = sum (T1); C2 = dis[row]*sum (T2)
// mode 2: C = [relu]( dis*(sum + 2*dis*C2in) + bias ); optional fused score.
__global__ void k_reduce(const float* __restrict__ P, int S, int M, int N, int mode,
                         const float* __restrict__ dis, const float* __restrict__ bias,
                         float* __restrict__ C, float* __restrict__ C2, int relu,
                         const float* __restrict__ p, const float* __restrict__ pnP,
                         float* __restrict__ scoreP) {
    int tid = threadIdx.x;
    int idx = blockIdx.x * blockDim.x + tid;
    int total = M * N;
    if (idx >= total) return;
    float s = 0.0f;
    for (int z = 0; z < S; z++) s += P[(size_t)z * total + idx];
    int gm = idx / N;
    int gn = idx - gm * N;
    if (mode == 0) {
        C[idx] = s;
        C2[idx] = dis[gm] * s;
    } else {
        float di = dis[gm];
        float v = di * (s + 2.0f * di * C2[idx]) + bias[gn];
        if (relu) v = fmaxf(v, 0.0f);
        C[idx] = v;
        if (scoreP) {
            __shared__ float sm[256];
            sm[tid] = v * p[gn];
            __syncthreads();
            for (int o = 64; o > 0; o >>= 1) {
                if ((tid & 127) < o) sm[tid] += sm[tid + o];
                __syncthreads();
            }
            if ((tid & 127) == 0) scoreP[gm] = sm[tid] / pnP[0];
        }
    }
}

// Per-row reduce of augment partials: zero diag, write A, rowsum -> dis.
__global__ void k_reduce_dis(const float* __restrict__ P, int S, int k,
                             float* __restrict__ A, float* __restrict__ dis) {
    __shared__ float red[8];
    int r = blockIdx.x;
    int tid = threadIdx.x;
    float s = 0.0f;
    for (int c = tid; c < k; c += 256) {
        float v = 0.0f;
        for (int z = 0; z < S; z++) v += P[(size_t)z * k * k + (size_t)r * k + c];
        if (c == r) v = 0.0f;
        s += v;
        A[(size_t)r * k + c] = v;
    }
    int lane = tid & 31, w = tid >> 5;
#pragma unroll
    for (int off = 16; off; off >>= 1) s += __shfl_down_sync(0xffffffffu, s, off);
    if (lane == 0) red[w] = s;
    __syncthreads();
    if (tid == 0) {
        float tot = 0.0f;
#pragma unroll
        for (int i = 0; i < 8; i++) tot += red[i];
        dis[r] = rsqrtf(tot + 2.0f);
    }
}

// Q[m, c] = B1[m, perm[c]]  (column gather with diag patch)
__global__ void k_gather_cols(const float* __restrict__ A, const int* __restrict__ perm,
                              float* __restrict__ Q, int k, int n) {
    size_t idx = (size_t)blockIdx.x * blockDim.x + threadIdx.x;
    if (idx < (size_t)n * k) {
        int m = (int)(idx / k), c = (int)(idx % k);
        int pc = perm[c];
        float v = A[(size_t)m * n + pc];
        Q[idx] = (m == pc) ? 1.0f : v;
    }
}

// ---------------- pooling ----------------

// Packed-key bitonic sort with warp-fused tail (j<=16 via shfl_xor).
__global__ void k_topk_sort(const float* __restrict__ score, int n, int k,
                            int* __restrict__ perm, float* __restrict__ vals,
                            int* __restrict__ inv) {
    __shared__ unsigned long long key[4096];
    int tid = threadIdx.x;
    int lane = tid & 31, w = tid >> 5;
    int numWarps = blockDim.x >> 5;
    for (int i = tid; i < n; i += blockDim.x) {
        unsigned u = __float_as_uint(score[i]);
        u = (u & 0x80000000u) ? ~u : (u | 0x80000000u);
        key[i] = ((unsigned long long)u << 32) | (unsigned)(~i);
        inv[i] = -1;
    }
    __syncthreads();
    int half = n >> 1;
    for (int ksz = 2; ksz <= n; ksz <<= 1) {
        for (int j = ksz >> 1; j >= 32; j >>= 1) {
            for (int p = tid; p < half; p += blockDim.x) {
                int idx = ((p & ~(j - 1)) << 1) | (p & (j - 1));
                int ixj = idx | j;
                unsigned long long a = key[idx], b = key[ixj];
                bool dir = (idx & ksz) == 0;
                if (dir ? (b > a) : (a > b)) { key[idx] = b; key[ixj] = a; }
            }
            __syncthreads();
        }
        int jstart = (ksz >> 1 < 16) ? (ksz >> 1) : 16;
        for (int seg = w; seg < (n >> 5); seg += numWarps) {
            int idx = (seg << 5) | lane;
            unsigned long long v = key[idx];
            bool dir = (idx & ksz) == 0;
            for (int j = jstart; j >= 1; j >>= 1) {
                unsigned long long o = __shfl_xor_sync(0xffffffffu, v, j);
                bool lower = (lane & j) == 0;
                bool takeMax = (dir == lower);
                bool gt = (v > o);
                v = (takeMax == gt) ? v : o;
            }
            key[idx] = v;
        }
        __syncthreads();
    }
    for (int r = tid; r < k; r += blockDim.x) {
        int idx = (int)(~(unsigned)key[r]);
        perm[r] = idx;
        vals[r] = score[idx];
        inv[idx] = r;
    }
}

// ---------------- final conv (unpool fused) ----------------

__global__ void k_hw_out_uf(const float* __restrict__ X0, const float* __restrict__ h,
                            const int* __restrict__ inv, const float* __restrict__ Wout,
                            const float* __restrict__ dis, float* __restrict__ hw,
                            float* __restrict__ g) {
    int i = blockIdx.x;
    int c = threadIdx.x;
    float v = X0[i * HID + c];
    int r = inv[i];
    if (r >= 0) v += h[r * HID + c];
    __shared__ float sm[HID];
    sm[c] = v * Wout[c];
    __syncthreads();
    for (int o = 64; o > 0; o >>= 1) {
        if (c < o) sm[c] += sm[c + o];
        __syncthreads();
    }
    if (c == 0) { hw[i] = sm[0]; g[i] = dis[i] * sm[0]; }
}

__global__ void k_final_sp(const int* __restrict__ rp, const int* __restrict__ colA,
                           const float* __restrict__ g, const float* __restrict__ hw,
                           const float* __restrict__ dis, const float* __restrict__ b,
                           float* __restrict__ out) {
    int i = blockIdx.x * blockDim.x + threadIdx.x;
    if (i < N0) {
        float s = 0.0f;
        int a = rp[i], e = rp[i + 1];
        for (int t = a; t < e; t++) s += g[colA[t]];
        float di = dis[i];
        out[i] = di * (s + 2.0f * di * hw[i]) + b[0];
    }
}

// ---------------- host orchestration ----------------

static float* g_split = nullptr;

// h@W: direct S=1 epilogue when grid large (n>=2048); split-K otherwise.
static void hW(const float* Hin, const float* W, int n, int S, const float* dis,
               const int* perm, const float* vals, const float* Xs, const int* inv,
               float* T1, float* T2) {
    if (n >= 2048) {
        dim3 g(2, n / 64, 1);
        k_gemm_sk<<<g, 256>>>(Hin, W, nullptr, n, HID, HID, HID, perm, vals, Xs, inv,
                              T1, T2, dis);
    } else {
        dim3 g(2, n / 64, S);
        k_gemm_sk<<<g, 256>>>(Hin, W, g_split, n, HID, HID, HID / S, perm, vals, Xs, inv,
                              nullptr, nullptr, nullptr);
        int total = n * HID;
        k_reduce<<<total / 256, 256>>>(g_split, S, n, HID, 0, dis, nullptr,
                                       T1, T2, 0, nullptr, nullptr, nullptr);
    }
}

static void at2(const float* A, const float* T2, const float* T1, int n, int S,
                const float* dis, const float* bias, float* C, int relu,
                const float* p, const float* pnP, float* score) {
    dim3 g(2, n / 64, S);
    k_gemm_sk<<<g, 256>>>(A, T2, g_split, n, HID, n, n / S,
                          nullptr, nullptr, nullptr, nullptr,
                          nullptr, nullptr, nullptr);
    int total = n * HID;
    k_reduce<<<total / 256, 256>>>(g_split, S, n, HID, 2, dis, bias,
                                   C, (float*)T1, relu, p, pnP, score);
}

extern "C" void kernel_launch(void* const* d_in, const int* in_sizes, int n_in,
                              void* d_out, int out_size) {
    const float* x      = (const float*)d_in[0];
    const int*   ei     = (const int*)d_in[1];
    const float* W_enc  = (const float*)d_in[3];
    const float* b_enc  = (const float*)d_in[4];
    const float* W_down = (const float*)d_in[5];
    const float* b_down = (const float*)d_in[6];
    const float* W_up   = (const float*)d_in[7];
    const float* b_up   = (const float*)d_in[8];
    const float* W_out  = (const float*)d_in[9];
    const float* b_out  = (const float*)d_in[10];
    const float* p_pool = (const float*)d_in[11];
    float* out = (float*)d_out;

    float *A2, *A3, *A4, *Qb;
    float *X0, *X1, *X2, *X3, *Ha, *Hb, *T1, *T2;
    float *Score, *Vals, *HWo, *Gv, *Pn;
    float *A1vals;
    int *A1cols, *A1cnt;
    int *P0, *P1, *P2, *P3, *Rp, *ColA, *Cnt, *Cur;
    int *I0, *I1, *I2, *I3;
    float *D0, *D1, *D2, *D3, *D4;
    cudaGetSymbolAddress((void**)&A1cols, dA1cols);
    cudaGetSymbolAddress((void**)&A1vals, dA1vals);
    cudaGetSymbolAddress((void**)&A1cnt, dA1cnt);
    cudaGetSymbolAddress((void**)&A2, dA2);
    cudaGetSymbolAddress((void**)&A3, dA3);
    cudaGetSymbolAddress((void**)&A4, dA4);
    cudaGetSymbolAddress((void**)&g_split, dSplit);
    cudaGetSymbolAddress((void**)&Qb, dQbuf);
    cudaGetSymbolAddress((void**)&X0, dX0);
    cudaGetSymbolAddress((void**)&X1, dX1);
    cudaGetSymbolAddress((void**)&X2, dX2);
    cudaGetSymbolAddress((void**)&X3, dX3);
    cudaGetSymbolAddress((void**)&Ha, dHa);
    cudaGetSymbolAddress((void**)&Hb, dHb);
    cudaGetSymbolAddress((void**)&T1, dT1);
    cudaGetSymbolAddress((void**)&T2, dT2);
    cudaGetSymbolAddress((void**)&Score, dScore);
    cudaGetSymbolAddress((void**)&Vals, dValsArr);
    cudaGetSymbolAddress((void**)&HWo, dHWo);
    cudaGetSymbolAddress((void**)&Gv, dGv);
    cudaGetSymbolAddress((void**)&Pn, dPn);
    cudaGetSymbolAddress((void**)&P0, dPerm0);
    cudaGetSymbolAddress((void**)&P1, dPerm1);
    cudaGetSymbolAddress((void**)&P2, dPerm2);
    cudaGetSymbolAddress((void**)&P3, dPerm3);
    cudaGetSymbolAddress((void**)&I0, dInv0);
    cudaGetSymbolAddress((void**)&I1, dInv1);
    cudaGetSymbolAddress((void**)&I2, dInv2);
    cudaGetSymbolAddress((void**)&I3, dInv3);
    cudaGetSymbolAddress((void**)&D0, dDis0);
    cudaGetSymbolAddress((void**)&D1, dDis1);
    cudaGetSymbolAddress((void**)&D2, dDis2);
    cudaGetSymbolAddress((void**)&D3, dDis3);
    cudaGetSymbolAddress((void**)&D4, dDis4);
    cudaGetSymbolAddress((void**)&Rp, dRp);
    cudaGetSymbolAddress((void**)&ColA, dColA);
    cudaGetSymbolAddress((void**)&Cnt, dCnt);
    cudaGetSymbolAddress((void**)&Cur, dCur);

    // 1) node encoder + CSR of A0 (dis0 + p-norms fused into scan;
    //    Cnt/Cur zeroing self-cleaned inside k_scan_dis)
    k_encoder<<<N0, HID>>>(x, W_enc, b_enc, Ha);
    k_count<<<EDGES / 256, 256>>>(ei, Cnt);
    k_scan_dis<<<1, 1024>>>(Cnt, Cur, Rp, D0, p_pool, Pn);
    k_fill<<<EDGES / 256, 256>>>(ei, Rp, Cur, ColA);

    // 2) down conv 0 (sparse, direct-epilogue GEMM, score fused) -> X0, Score
    hW(Ha, W_down, N0, 1, D0, nullptr, nullptr, nullptr, nullptr, T1, T2);
    k_spmm0_ep<<<N0 / 8, 256>>>(Rp, ColA, T2, T1, D0, b_down, X0, 1,
                                p_pool, Pn, Score);

    // 3) down level 1 (sparse A1); pool fused into hW; score fused into spmm
    k_topk_sort<<<1, 1024>>>(Score, 4096, 2048, P0, Vals, I0);
    k_spgemm1<<<2048, 256>>>(Rp, ColA, P0, I0, A1cols, A1vals, A1cnt, D1);
    hW(X0, W_down + 1 * HID * HID, 2048, 1, D1, P0, Vals, nullptr, nullptr, T1, T2);
    k_spmm1_ep<<<2048 / 8, 256>>>(A1cols, A1vals, A1cnt, T2, T1, D1,
                                  b_down + 1 * HID, X1, 1,
                                  p_pool + HID, Pn + 1, Score);

    // 4) down level 2 (dense A2 via sparse spgemm); score fused into reduce
    k_topk_sort<<<1, 1024>>>(Score, 2048, 1024, P1, Vals, I1);
    k_spgemm2<<<1024, 256>>>(A1cols, A1vals, A1cnt, P1, I1, A2, D2, 1024);
    hW(X1, W_down + 2 * HID * HID, 1024, 4, D2, P1, Vals, nullptr, nullptr, T1, T2);
    at2(A2, T2, T1, 1024, 8, D2, b_down + 2 * HID, X2, 1,
        p_pool + 2 * HID, Pn + 2, Score);

    // 5) down level 3 (dense augment from A2)
    k_topk_sort<<<1, 1024>>>(Score, 1024, 512, P2, Vals, I2);
    {
        size_t t = (size_t)1024 * 512;
        k_gather_cols<<<(unsigned)((t + 255) / 256), 256>>>(A2, P2, Qb, 512, 1024);
        dim3 gg(512 / 64, 512 / 64, 4);
        k_gemm_aug<<<gg, 256>>>(A2, P2, Qb, g_split, 512, 1024, 256);
        k_reduce_dis<<<512, 256>>>(g_split, 4, 512, A3, D3);
    }
    hW(X2, W_down + 3 * HID * HID, 512, 8, D3, P2, Vals, nullptr, nullptr, T1, T2);
    at2(A3, T2, T1, 512, 16, D3, b_down + 3 * HID, X3, 1,
        p_pool + 3 * HID, Pn + 3, Score);

    // 6) down level 4 (dense augment from A3)
    k_topk_sort<<<1, 1024>>>(Score, 512, 256, P3, Vals, I3);
    {
        size_t t = (size_t)512 * 256;
        k_gather_cols<<<(unsigned)((t + 255) / 256), 256>>>(A3, P3, Qb, 256, 512);
        dim3 gg(256 / 64, 256 / 64, 16);
        k_gemm_aug<<<gg, 256>>>(A3, P3, Qb, g_split, 256, 512, 32);
        k_reduce_dis<<<256, 256>>>(g_split, 16, 256, A4, D4);
    }
    hW(X3, W_down + 4 * HID * HID, 256, 8, D4, P3, Vals, nullptr, nullptr, T1, T2);
    at2(A4, T2, T1, 256, 16, D4, b_down + 4 * HID, Hb, 1, nullptr, nullptr, nullptr);

    // 7) up path (unpool fused into hW A-loads)
    // j = 3 (n = 512)
    hW(Hb, W_up, 512, 8, D3, nullptr, nullptr, X3, I3, T1, T2);
    at2(A3, T2, T1, 512, 16, D3, b_up, Hb, 1, nullptr, nullptr, nullptr);
    // j = 2 (n = 1024)
    hW(Hb, W_up + 1 * HID * HID, 1024, 4, D2, nullptr, nullptr, X2, I2, T1, T2);
    at2(A2, T2, T1, 1024, 8, D2, b_up + 1 * HID, Hb, 1, nullptr, nullptr, nullptr);
    // j = 1 (n = 2048, sparse A1)
    hW(Hb, W_up + 2 * HID * HID, 2048, 1, D1, nullptr, nullptr, X1, I1, T1, T2);
    k_spmm1_ep<<<2048 / 8, 256>>>(A1cols, A1vals, A1cnt, T2, T1, D1,
                                  b_up + 2 * HID, Hb, 1,
                                  nullptr, nullptr, nullptr);
    // j = 0 (n = 4096, final conv HID->1 on CSR A0)
    k_hw_out_uf<<<N0, HID>>>(X0, Hb, I0, W_out, D0, HWo, Gv);
    k_final_sp<<<(N0 + 127) / 128, 128>>>(Rp, ColA, Gv, HWo, D0, b_out, out);
}